// round 8
// baseline (speedup 1.0000x reference)
#include <cuda_runtime.h>
#include <cuda_bf16.h>

// 10-qubit, batch-16384 circuit: RY embedding + 2x StronglyEntanglingLayers.
// R7 = R6 with kM2 epilogue access moved behind a template (compile-time only).
// Compact 4-scalar Rot coefficients, WHT epilogue, folded prologue, 3 blk/SM.
// CNOTs eliminated via GF(2) relabeling; packed f32x2 complex math.

#define N_QUBITS 10
#define BATCH    16384

using ull = unsigned long long;

// ---------------- constexpr GF(2) relabeling ----------------
struct M10 { unsigned r[10]; };

__host__ __device__ constexpr M10 mident() {
    M10 m{}; for (int b = 0; b < 10; b++) m.r[b] = 1u << b; return m;
}
__host__ __device__ constexpr M10 mring(M10 m, int rr) {
    for (int q = 0; q < 10; q++) {
        int t = (q + rr) % 10;
        m.r[9 - t] ^= m.r[9 - q];
    }
    return m;
}
__host__ __device__ constexpr M10 minv(M10 a) {
    M10 inv = mident();
    for (int col = 0; col < 10; col++) {
        int piv = col;
        while (!((a.r[piv] >> col) & 1)) piv++;
        unsigned t = a.r[col]; a.r[col] = a.r[piv]; a.r[piv] = t;
        t = inv.r[col]; inv.r[col] = inv.r[piv]; inv.r[piv] = t;
        for (int r2 = 0; r2 < 10; r2++)
            if (r2 != col && ((a.r[r2] >> col) & 1)) { a.r[r2] ^= a.r[col]; inv.r[r2] ^= inv.r[col]; }
    }
    return inv;
}
__host__ __device__ constexpr unsigned mcol(M10 n, int b) {
    unsigned w = 0;
    for (int sb = 0; sb < 10; sb++) if ((n.r[sb] >> b) & 1) w |= 1u << sb;
    return w;
}
__host__ __device__ constexpr unsigned hibit(unsigned x) {
    unsigned b = 1; while (x >> 1) { x >>= 1; b <<= 1; } return b;
}

constexpr M10 kM1 = mring(mident(), 1);
constexpr M10 kN1 = minv(kM1);
constexpr M10 kM2 = mring(kM1, 2);

// ---------------- packed f32x2 primitives ----------------
__device__ __forceinline__ ull pk2(float lo, float hi) {
    ull u; asm("mov.b64 %0, {%1, %2};" : "=l"(u) : "f"(lo), "f"(hi)); return u;
}
__device__ __forceinline__ void un2(ull u, float& a, float& b) {
    asm("mov.b64 {%0, %1}, %2;" : "=f"(a), "=f"(b) : "l"(u));
}
__device__ __forceinline__ ull fma2(ull a, ull b, ull c) {
    ull d; asm("fma.rn.f32x2 %0, %1, %2, %3;" : "=l"(d) : "l"(a), "l"(b), "l"(c)); return d;
}
__device__ __forceinline__ ull mul2(ull a, ull b) {
    ull d; asm("mul.rn.f32x2 %0, %1, %2;" : "=l"(d) : "l"(a), "l"(b)); return d;
}
__device__ __forceinline__ ull add2(ull a, ull b) {
    ull d; asm("add.rn.f32x2 %0, %1, %2;" : "=l"(d) : "l"(a), "l"(b)); return d;
}
__device__ __forceinline__ ull shfl64x(ull v, int m) {
    float a, b; un2(v, a, b);
    a = __shfl_xor_sync(0xFFFFFFFFu, a, m);
    b = __shfl_xor_sync(0xFFFFFFFFu, b, m);
    return pk2(a, b);
}
__device__ __forceinline__ ull swap2(ull v) {
    float a, b; un2(v, a, b); return pk2(b, a);
}

// ---------------- precomputed compact Rot coefficients ----------------
// Rot = [[P - iQ, -R - iS], [R - iS, P + iQ]] with
// P=cos((phi+omega)/2)cos(th/2), Q=sin((phi+omega)/2)cos(th/2),
// R=cos((phi-omega)/2)sin(th/2), S=sin((phi-omega)/2)sin(th/2).
__device__ float4 g_rotc[2 * N_QUBITS];

__global__ void precompute_rot_kernel(const float* __restrict__ qw) {
    int i = threadIdx.x;
    if (i < 2 * N_QUBITS) {
        float phi = qw[i * 3 + 0], theta = qw[i * 3 + 1], omega = qw[i * 3 + 2];
        float st, ct;   sincosf(0.5f * theta, &st, &ct);
        float spo, cpo; sincosf(0.5f * (phi + omega), &spo, &cpo);
        float smo, cmo; sincosf(0.5f * (phi - omega), &smo, &cmo);
        g_rotc[i] = make_float4(cpo * ct, spo * ct, cmo * st, smo * st);
    }
}

// ---------------- generalized single-qubit gate ----------------
// Pairs stored s with s^W; role parity(s & R) selects matrix row.
// Update with sigma = +1 (role0) / -1 (role1):
//   re' = P*ar + S*oi + sigma*(Q*ai - R*or)
//   im' = P*ai - S*or + sigma*(-Q*ar - R*oi)
template <unsigned W, unsigned R>
__device__ __forceinline__ void gate(ull* rr, ull* ii, int lane, float4 m) {
    constexpr unsigned wl = W & 31u;
    constexpr unsigned wh = (W >> 5) & 31u;
    constexpr unsigned rl = R & 31u;
    constexpr unsigned rh = (R >> 5) & 31u;
    constexpr unsigned pw = wl >> 1;
    constexpr unsigned pr = rl >> 1;
    constexpr bool xh  = (wl & 1u) != 0;
    constexpr bool rhd = (rl & 1u) != 0;

    const unsigned lane_par = (0x96696996u >> (lane & rh)) & 1u;
    const float sp = lane_par ? -1.0f : 1.0f;      // sigma for half-lo, parity0
    const float sh = rhd ? -sp : sp;               // sigma for half-hi, parity0

    const ull P2  = pk2(m.x, m.x);
    const ull Sv2 = pk2(m.w, m.w);
    const ull nS2 = pk2(-m.w, -m.w);
    const ull QA  = pk2(sp * m.y, sh * m.y);
    const ull nQA = pk2(-sp * m.y, -sh * m.y);
    const ull RA  = pk2(sp * m.z, sh * m.z);
    const ull nRA = pk2(-sp * m.z, -sh * m.z);

#define CUPD(nre, nim, are, aie, ore, oie, PAR)                       \
    {                                                                 \
        ull Qp_ = (PAR) ? nQA : QA;                                   \
        ull Qm_ = (PAR) ? QA : nQA;                                   \
        ull Rp_ = (PAR) ? RA : nRA;                                   \
        ull t1_ = fma2(Qp_, (aie), mul2(Rp_, (ore)));                 \
        ull t2_ = fma2(Qm_, (are), mul2(Rp_, (oie)));                 \
        (nre) = fma2(P2, (are), fma2(Sv2, (oie), t1_));               \
        (nim) = fma2(P2, (aie), fma2(nS2, (ore), t2_));               \
    }

    if constexpr (pw == 0) {
#pragma unroll
        for (int p = 0; p < 16; p++) {
            ull ore = rr[p], oie = ii[p];
            if constexpr (wh != 0) { ore = shfl64x(ore, (int)wh); oie = shfl64x(oie, (int)wh); }
            if constexpr (xh)      { ore = swap2(ore); oie = swap2(oie); }
            const bool PAR = ((0x6996u >> (p & pr)) & 1u) != 0;
            ull nre, nim;
            CUPD(nre, nim, rr[p], ii[p], ore, oie, PAR);
            rr[p] = nre; ii[p] = nim;
        }
    } else {
        constexpr unsigned selbit = hibit(pw);
#pragma unroll
        for (int p = 0; p < 16; p++) {
            if (p & (int)selbit) continue;
            const int p2 = p ^ (int)pw;
            ull oa_re = rr[p2], oa_ie = ii[p2];
            ull ob_re = rr[p],  ob_ie = ii[p];
            if constexpr (wh != 0) {
                oa_re = shfl64x(oa_re, (int)wh); oa_ie = shfl64x(oa_ie, (int)wh);
                ob_re = shfl64x(ob_re, (int)wh); ob_ie = shfl64x(ob_ie, (int)wh);
            }
            if constexpr (xh) {
                oa_re = swap2(oa_re); oa_ie = swap2(oa_ie);
                ob_re = swap2(ob_re); ob_ie = swap2(ob_ie);
            }
            const bool pA = ((0x6996u >> (p  & pr)) & 1u) != 0;
            const bool pC = ((0x6996u >> (p2 & pr)) & 1u) != 0;
            ull nre1, nim1, nre2, nim2;
            CUPD(nre1, nim1, rr[p],  ii[p],  oa_re, oa_ie, pA);
            CUPD(nre2, nim2, rr[p2], ii[p2], ob_re, ob_ie, pC);
            rr[p] = nre1; ii[p] = nim1; rr[p2] = nre2; ii[p2] = nim2;
        }
    }
#undef CUPD
}

template <int Q>
__device__ __forceinline__ void apply_l1(ull* rr, ull* ii, int lane) {
    constexpr int b = 9 - Q;
    constexpr unsigned W = mcol(kN1, b);
    constexpr unsigned R = kM1.r[b];
    float4 m = __ldg(&g_rotc[N_QUBITS + Q]);
    gate<W, R>(rr, ii, lane, m);
}

// <Z_wireQ> from WHT array (compile-time mask extraction; kM2 not ODR-used).
template <int Q>
__device__ __forceinline__ float expz_wht(const ull* pp, int lane) {
    constexpr unsigned mr = kM2.r[9 - Q];
    constexpr unsigned rl = mr & 31u;
    constexpr unsigned rh = (mr >> 5) & 31u;
    constexpr unsigned ps = rl >> 1;
    float a, b; un2(pp[ps], a, b);
    float z = (rl & 1u) ? (a - b) : (a + b);
    if ((0x96696996u >> (lane & rh)) & 1u) z = -z;
    return z;
}

__device__ __forceinline__ float2 cmul(float2 a, float2 b) {
    return make_float2(a.x * b.x - a.y * b.y, a.x * b.y + a.y * b.x);
}

// ---------------- main kernel ----------------
__global__ void __launch_bounds__(256, 3)
sim_kernel(const float* __restrict__ x, float* __restrict__ out) {
    const int warp = (blockIdx.x * blockDim.x + threadIdx.x) >> 5;
    const int lane = threadIdx.x & 31;
    if (warp >= BATCH) return;

    const float* xs = x + warp * N_QUBITS;

    // ---- Prologue: per-wire factors after RY(x_q) then Rot(l=0,q) ----
    // f0 = (P c - R s, -(Q c + S s)); f1 = (R c + P s, Q s - S c)
    // Wires 0..4 are lane bits (lane bit j <-> wire 4-j): fold immediately.
    float2 lf = make_float2(1.0f, 0.0f);
#pragma unroll
    for (int j = 0; j < 5; j++) {
        const int q = 4 - j;
        float s, c; sincosf(0.5f * __ldg(&xs[q]), &s, &c);
        float4 m = __ldg(&g_rotc[q]);
        float2 f;
        if ((lane >> j) & 1)
            f = make_float2(fmaf(m.z, c, m.x * s), fmaf(m.y, s, -m.w * c));
        else
            f = make_float2(fmaf(m.x, c, -m.z * s), -fmaf(m.y, c, m.w * s));
        lf = cmul(lf, f);
    }

    // Wires 5..9 are local bits (stored bit j <-> wire 9-j; pack half = wire 9).
    float2 f0[5], f1[5];  // index j: wire 9-j
#pragma unroll
    for (int j = 0; j < 5; j++) {
        const int q = 9 - j;
        float s, c; sincosf(0.5f * __ldg(&xs[q]), &s, &c);
        float4 m = __ldg(&g_rotc[q]);
        f0[j] = make_float2(fmaf(m.x, c, -m.z * s), -fmaf(m.y, c, m.w * s));
        f1[j] = make_float2(fmaf(m.z, c, m.x * s), fmaf(m.y, s, -m.w * c));
    }

    // Local product tree over pack-half (wire 9) and p bits (wires 8..5).
    ull rr[16], ii[16];
    {
        float2 a0 = cmul(f0[0], lf);
        float2 a1 = cmul(f1[0], lf);
        rr[0] = pk2(a0.x, a1.x); ii[0] = pk2(a0.y, a1.y);
    }
#pragma unroll
    for (int j = 1; j < 5; j++) {
        const int n = 1 << (j - 1);
        float2 w0 = f0[j], w1 = f1[j];
        ull w0re = pk2(w0.x, w0.x), w0im = pk2(w0.y, w0.y), w0mn = pk2(-w0.y, -w0.y);
        ull w1re = pk2(w1.x, w1.x), w1im = pk2(w1.y, w1.y), w1mn = pk2(-w1.y, -w1.y);
#pragma unroll
        for (int p = 0; p < n; p++) {
            ull zr = rr[p], zi = ii[p];
            rr[p | n] = fma2(w1re, zr, mul2(w1mn, zi));
            ii[p | n] = fma2(w1re, zi, mul2(w1im, zr));
            rr[p]     = fma2(w0re, zr, mul2(w0mn, zi));
            ii[p]     = fma2(w0re, zi, mul2(w0im, zr));
        }
    }
    // State == embedding + layer0 Rots; layer0 CNOT ring absorbed into masks.

    // ---- Layer-1 Rot gates in relabeled basis ----
    apply_l1<0>(rr, ii, lane);
    apply_l1<1>(rr, ii, lane);
    apply_l1<2>(rr, ii, lane);
    apply_l1<3>(rr, ii, lane);
    apply_l1<4>(rr, ii, lane);
    apply_l1<5>(rr, ii, lane);
    apply_l1<6>(rr, ii, lane);
    apply_l1<7>(rr, ii, lane);
    apply_l1<8>(rr, ii, lane);
    apply_l1<9>(rr, ii, lane);
    // Layer-1 CNOT ring absorbed into measurement masks (kM2).

    // ---- Probabilities + Walsh-Hadamard over the 4 p-bits ----
    ull pp[16];
#pragma unroll
    for (int p = 0; p < 16; p++) pp[p] = fma2(rr[p], rr[p], mul2(ii[p], ii[p]));

    const ull kNeg1 = pk2(-1.0f, -1.0f);
#pragma unroll
    for (int b = 1; b < 16; b <<= 1) {
#pragma unroll
        for (int p = 0; p < 16; p++) {
            if (p & b) continue;
            ull u = pp[p], v = pp[p | b];
            pp[p]     = add2(u, v);
            pp[p | b] = fma2(v, kNeg1, u);  // u - v
        }
    }
    // pp[mask] = sum_p (-1)^{parity(p & mask)} |amp|^2 (packed per half)

    float zv[10];
    zv[0] = expz_wht<0>(pp, lane);
    zv[1] = expz_wht<1>(pp, lane);
    zv[2] = expz_wht<2>(pp, lane);
    zv[3] = expz_wht<3>(pp, lane);
    zv[4] = expz_wht<4>(pp, lane);
    zv[5] = expz_wht<5>(pp, lane);
    zv[6] = expz_wht<6>(pp, lane);
    zv[7] = expz_wht<7>(pp, lane);
    zv[8] = expz_wht<8>(pp, lane);
    zv[9] = expz_wht<9>(pp, lane);

#pragma unroll
    for (int off = 16; off > 0; off >>= 1) {
#pragma unroll
        for (int q = 0; q < 10; q++)
            zv[q] += __shfl_xor_sync(0xFFFFFFFFu, zv[q], off);
    }

    if (lane == 0) {
        float* o = out + warp * N_QUBITS;
#pragma unroll
        for (int q = 0; q < N_QUBITS; q++) o[q] = zv[q];
    }
}

extern "C" void kernel_launch(void* const* d_in, const int* in_sizes, int n_in,
                              void* d_out, int out_size) {
    const float* x  = (const float*)d_in[0];  // [16384, 10]
    const float* qw = (const float*)d_in[1];  // [2, 10, 3]
    float* out = (float*)d_out;               // [16384, 10]

    precompute_rot_kernel<<<1, 32>>>(qw);

    const int threads = 256;
    const int blocks  = (BATCH * 32) / threads;
    sim_kernel<<<blocks, threads>>>(x, out);
}

// round 9
// speedup vs baseline: 1.0599x; 1.0599x over previous
#include <cuda_runtime.h>
#include <cuda_bf16.h>

// 10-qubit, batch-16384 circuit: RY embedding + 2x StronglyEntanglingLayers.
// R9 = R7 with launch config tuned to the no-spill point: 128 thr x 5 blk/SM
// (reg cap 102 >= ~95 natural demand, 20 warps/SM). Compact 4-scalar Rot
// coefficients, WHT epilogue, GF(2)-relabeled CNOTs, packed f32x2 math.

#define N_QUBITS 10
#define BATCH    16384

using ull = unsigned long long;

// ---------------- constexpr GF(2) relabeling ----------------
struct M10 { unsigned r[10]; };

__host__ __device__ constexpr M10 mident() {
    M10 m{}; for (int b = 0; b < 10; b++) m.r[b] = 1u << b; return m;
}
__host__ __device__ constexpr M10 mring(M10 m, int rr) {
    for (int q = 0; q < 10; q++) {
        int t = (q + rr) % 10;
        m.r[9 - t] ^= m.r[9 - q];
    }
    return m;
}
__host__ __device__ constexpr M10 minv(M10 a) {
    M10 inv = mident();
    for (int col = 0; col < 10; col++) {
        int piv = col;
        while (!((a.r[piv] >> col) & 1)) piv++;
        unsigned t = a.r[col]; a.r[col] = a.r[piv]; a.r[piv] = t;
        t = inv.r[col]; inv.r[col] = inv.r[piv]; inv.r[piv] = t;
        for (int r2 = 0; r2 < 10; r2++)
            if (r2 != col && ((a.r[r2] >> col) & 1)) { a.r[r2] ^= a.r[col]; inv.r[r2] ^= inv.r[col]; }
    }
    return inv;
}
__host__ __device__ constexpr unsigned mcol(M10 n, int b) {
    unsigned w = 0;
    for (int sb = 0; sb < 10; sb++) if ((n.r[sb] >> b) & 1) w |= 1u << sb;
    return w;
}
__host__ __device__ constexpr unsigned hibit(unsigned x) {
    unsigned b = 1; while (x >> 1) { x >>= 1; b <<= 1; } return b;
}

constexpr M10 kM1 = mring(mident(), 1);
constexpr M10 kN1 = minv(kM1);
constexpr M10 kM2 = mring(kM1, 2);

// ---------------- packed f32x2 primitives ----------------
__device__ __forceinline__ ull pk2(float lo, float hi) {
    ull u; asm("mov.b64 %0, {%1, %2};" : "=l"(u) : "f"(lo), "f"(hi)); return u;
}
__device__ __forceinline__ void un2(ull u, float& a, float& b) {
    asm("mov.b64 {%0, %1}, %2;" : "=f"(a), "=f"(b) : "l"(u));
}
__device__ __forceinline__ ull fma2(ull a, ull b, ull c) {
    ull d; asm("fma.rn.f32x2 %0, %1, %2, %3;" : "=l"(d) : "l"(a), "l"(b), "l"(c)); return d;
}
__device__ __forceinline__ ull mul2(ull a, ull b) {
    ull d; asm("mul.rn.f32x2 %0, %1, %2;" : "=l"(d) : "l"(a), "l"(b)); return d;
}
__device__ __forceinline__ ull add2(ull a, ull b) {
    ull d; asm("add.rn.f32x2 %0, %1, %2;" : "=l"(d) : "l"(a), "l"(b)); return d;
}
__device__ __forceinline__ ull shfl64x(ull v, int m) {
    float a, b; un2(v, a, b);
    a = __shfl_xor_sync(0xFFFFFFFFu, a, m);
    b = __shfl_xor_sync(0xFFFFFFFFu, b, m);
    return pk2(a, b);
}
__device__ __forceinline__ ull swap2(ull v) {
    float a, b; un2(v, a, b); return pk2(b, a);
}

// ---------------- precomputed compact Rot coefficients ----------------
// Rot = [[P - iQ, -R - iS], [R - iS, P + iQ]] with
// P=cos((phi+omega)/2)cos(th/2), Q=sin((phi+omega)/2)cos(th/2),
// R=cos((phi-omega)/2)sin(th/2), S=sin((phi-omega)/2)sin(th/2).
__device__ float4 g_rotc[2 * N_QUBITS];

__global__ void precompute_rot_kernel(const float* __restrict__ qw) {
    int i = threadIdx.x;
    if (i < 2 * N_QUBITS) {
        float phi = qw[i * 3 + 0], theta = qw[i * 3 + 1], omega = qw[i * 3 + 2];
        float st, ct;   sincosf(0.5f * theta, &st, &ct);
        float spo, cpo; sincosf(0.5f * (phi + omega), &spo, &cpo);
        float smo, cmo; sincosf(0.5f * (phi - omega), &smo, &cmo);
        g_rotc[i] = make_float4(cpo * ct, spo * ct, cmo * st, smo * st);
    }
}

// ---------------- generalized single-qubit gate ----------------
// Pairs stored s with s^W; role parity(s & R) selects matrix row.
// Update with sigma = +1 (role0) / -1 (role1):
//   re' = P*ar + S*oi + sigma*(Q*ai - R*or)
//   im' = P*ai - S*or + sigma*(-Q*ar - R*oi)
template <unsigned W, unsigned R>
__device__ __forceinline__ void gate(ull* rr, ull* ii, int lane, float4 m) {
    constexpr unsigned wl = W & 31u;
    constexpr unsigned wh = (W >> 5) & 31u;
    constexpr unsigned rl = R & 31u;
    constexpr unsigned rh = (R >> 5) & 31u;
    constexpr unsigned pw = wl >> 1;
    constexpr unsigned pr = rl >> 1;
    constexpr bool xh  = (wl & 1u) != 0;
    constexpr bool rhd = (rl & 1u) != 0;

    const unsigned lane_par = (0x96696996u >> (lane & rh)) & 1u;
    const float sp = lane_par ? -1.0f : 1.0f;      // sigma for half-lo, parity0
    const float sh = rhd ? -sp : sp;               // sigma for half-hi, parity0

    const ull P2  = pk2(m.x, m.x);
    const ull Sv2 = pk2(m.w, m.w);
    const ull nS2 = pk2(-m.w, -m.w);
    const ull QA  = pk2(sp * m.y, sh * m.y);
    const ull nQA = pk2(-sp * m.y, -sh * m.y);
    const ull RA  = pk2(sp * m.z, sh * m.z);
    const ull nRA = pk2(-sp * m.z, -sh * m.z);

#define CUPD(nre, nim, are, aie, ore, oie, PAR)                       \
    {                                                                 \
        ull Qp_ = (PAR) ? nQA : QA;                                   \
        ull Qm_ = (PAR) ? QA : nQA;                                   \
        ull Rp_ = (PAR) ? RA : nRA;                                   \
        ull t1_ = fma2(Qp_, (aie), mul2(Rp_, (ore)));                 \
        ull t2_ = fma2(Qm_, (are), mul2(Rp_, (oie)));                 \
        (nre) = fma2(P2, (are), fma2(Sv2, (oie), t1_));               \
        (nim) = fma2(P2, (aie), fma2(nS2, (ore), t2_));               \
    }

    if constexpr (pw == 0) {
#pragma unroll
        for (int p = 0; p < 16; p++) {
            ull ore = rr[p], oie = ii[p];
            if constexpr (wh != 0) { ore = shfl64x(ore, (int)wh); oie = shfl64x(oie, (int)wh); }
            if constexpr (xh)      { ore = swap2(ore); oie = swap2(oie); }
            const bool PAR = ((0x6996u >> (p & pr)) & 1u) != 0;
            ull nre, nim;
            CUPD(nre, nim, rr[p], ii[p], ore, oie, PAR);
            rr[p] = nre; ii[p] = nim;
        }
    } else {
        constexpr unsigned selbit = hibit(pw);
#pragma unroll
        for (int p = 0; p < 16; p++) {
            if (p & (int)selbit) continue;
            const int p2 = p ^ (int)pw;
            ull oa_re = rr[p2], oa_ie = ii[p2];
            ull ob_re = rr[p],  ob_ie = ii[p];
            if constexpr (wh != 0) {
                oa_re = shfl64x(oa_re, (int)wh); oa_ie = shfl64x(oa_ie, (int)wh);
                ob_re = shfl64x(ob_re, (int)wh); ob_ie = shfl64x(ob_ie, (int)wh);
            }
            if constexpr (xh) {
                oa_re = swap2(oa_re); oa_ie = swap2(oa_ie);
                ob_re = swap2(ob_re); ob_ie = swap2(ob_ie);
            }
            const bool pA = ((0x6996u >> (p  & pr)) & 1u) != 0;
            const bool pC = ((0x6996u >> (p2 & pr)) & 1u) != 0;
            ull nre1, nim1, nre2, nim2;
            CUPD(nre1, nim1, rr[p],  ii[p],  oa_re, oa_ie, pA);
            CUPD(nre2, nim2, rr[p2], ii[p2], ob_re, ob_ie, pC);
            rr[p] = nre1; ii[p] = nim1; rr[p2] = nre2; ii[p2] = nim2;
        }
    }
#undef CUPD
}

template <int Q>
__device__ __forceinline__ void apply_l1(ull* rr, ull* ii, int lane) {
    constexpr int b = 9 - Q;
    constexpr unsigned W = mcol(kN1, b);
    constexpr unsigned R = kM1.r[b];
    float4 m = __ldg(&g_rotc[N_QUBITS + Q]);
    gate<W, R>(rr, ii, lane, m);
}

// <Z_wireQ> from WHT array (compile-time mask extraction; kM2 not ODR-used).
template <int Q>
__device__ __forceinline__ float expz_wht(const ull* pp, int lane) {
    constexpr unsigned mr = kM2.r[9 - Q];
    constexpr unsigned rl = mr & 31u;
    constexpr unsigned rh = (mr >> 5) & 31u;
    constexpr unsigned ps = rl >> 1;
    float a, b; un2(pp[ps], a, b);
    float z = (rl & 1u) ? (a - b) : (a + b);
    if ((0x96696996u >> (lane & rh)) & 1u) z = -z;
    return z;
}

__device__ __forceinline__ float2 cmul(float2 a, float2 b) {
    return make_float2(a.x * b.x - a.y * b.y, a.x * b.y + a.y * b.x);
}

// ---------------- main kernel ----------------
__global__ void __launch_bounds__(128, 5)
sim_kernel(const float* __restrict__ x, float* __restrict__ out) {
    const int warp = (blockIdx.x * blockDim.x + threadIdx.x) >> 5;
    const int lane = threadIdx.x & 31;
    if (warp >= BATCH) return;

    const float* xs = x + warp * N_QUBITS;

    // ---- Prologue: per-wire factors after RY(x_q) then Rot(l=0,q) ----
    // f0 = (P c - R s, -(Q c + S s)); f1 = (R c + P s, Q s - S c)
    // Wires 0..4 are lane bits (lane bit j <-> wire 4-j): fold immediately.
    float2 lf = make_float2(1.0f, 0.0f);
#pragma unroll
    for (int j = 0; j < 5; j++) {
        const int q = 4 - j;
        float s, c; sincosf(0.5f * __ldg(&xs[q]), &s, &c);
        float4 m = __ldg(&g_rotc[q]);
        float2 f;
        if ((lane >> j) & 1)
            f = make_float2(fmaf(m.z, c, m.x * s), fmaf(m.y, s, -m.w * c));
        else
            f = make_float2(fmaf(m.x, c, -m.z * s), -fmaf(m.y, c, m.w * s));
        lf = cmul(lf, f);
    }

    // Wires 5..9 are local bits (stored bit j <-> wire 9-j; pack half = wire 9).
    float2 f0[5], f1[5];  // index j: wire 9-j
#pragma unroll
    for (int j = 0; j < 5; j++) {
        const int q = 9 - j;
        float s, c; sincosf(0.5f * __ldg(&xs[q]), &s, &c);
        float4 m = __ldg(&g_rotc[q]);
        f0[j] = make_float2(fmaf(m.x, c, -m.z * s), -fmaf(m.y, c, m.w * s));
        f1[j] = make_float2(fmaf(m.z, c, m.x * s), fmaf(m.y, s, -m.w * c));
    }

    // Local product tree over pack-half (wire 9) and p bits (wires 8..5).
    ull rr[16], ii[16];
    {
        float2 a0 = cmul(f0[0], lf);
        float2 a1 = cmul(f1[0], lf);
        rr[0] = pk2(a0.x, a1.x); ii[0] = pk2(a0.y, a1.y);
    }
#pragma unroll
    for (int j = 1; j < 5; j++) {
        const int n = 1 << (j - 1);
        float2 w0 = f0[j], w1 = f1[j];
        ull w0re = pk2(w0.x, w0.x), w0im = pk2(w0.y, w0.y), w0mn = pk2(-w0.y, -w0.y);
        ull w1re = pk2(w1.x, w1.x), w1im = pk2(w1.y, w1.y), w1mn = pk2(-w1.y, -w1.y);
#pragma unroll
        for (int p = 0; p < n; p++) {
            ull zr = rr[p], zi = ii[p];
            rr[p | n] = fma2(w1re, zr, mul2(w1mn, zi));
            ii[p | n] = fma2(w1re, zi, mul2(w1im, zr));
            rr[p]     = fma2(w0re, zr, mul2(w0mn, zi));
            ii[p]     = fma2(w0re, zi, mul2(w0im, zr));
        }
    }
    // State == embedding + layer0 Rots; layer0 CNOT ring absorbed into masks.

    // ---- Layer-1 Rot gates in relabeled basis ----
    apply_l1<0>(rr, ii, lane);
    apply_l1<1>(rr, ii, lane);
    apply_l1<2>(rr, ii, lane);
    apply_l1<3>(rr, ii, lane);
    apply_l1<4>(rr, ii, lane);
    apply_l1<5>(rr, ii, lane);
    apply_l1<6>(rr, ii, lane);
    apply_l1<7>(rr, ii, lane);
    apply_l1<8>(rr, ii, lane);
    apply_l1<9>(rr, ii, lane);
    // Layer-1 CNOT ring absorbed into measurement masks (kM2).

    // ---- Probabilities + Walsh-Hadamard over the 4 p-bits ----
    ull pp[16];
#pragma unroll
    for (int p = 0; p < 16; p++) pp[p] = fma2(rr[p], rr[p], mul2(ii[p], ii[p]));

    const ull kNeg1 = pk2(-1.0f, -1.0f);
#pragma unroll
    for (int b = 1; b < 16; b <<= 1) {
#pragma unroll
        for (int p = 0; p < 16; p++) {
            if (p & b) continue;
            ull u = pp[p], v = pp[p | b];
            pp[p]     = add2(u, v);
            pp[p | b] = fma2(v, kNeg1, u);  // u - v
        }
    }
    // pp[mask] = sum_p (-1)^{parity(p & mask)} |amp|^2 (packed per half)

    float zv[10];
    zv[0] = expz_wht<0>(pp, lane);
    zv[1] = expz_wht<1>(pp, lane);
    zv[2] = expz_wht<2>(pp, lane);
    zv[3] = expz_wht<3>(pp, lane);
    zv[4] = expz_wht<4>(pp, lane);
    zv[5] = expz_wht<5>(pp, lane);
    zv[6] = expz_wht<6>(pp, lane);
    zv[7] = expz_wht<7>(pp, lane);
    zv[8] = expz_wht<8>(pp, lane);
    zv[9] = expz_wht<9>(pp, lane);

#pragma unroll
    for (int off = 16; off > 0; off >>= 1) {
#pragma unroll
        for (int q = 0; q < 10; q++)
            zv[q] += __shfl_xor_sync(0xFFFFFFFFu, zv[q], off);
    }

    if (lane == 0) {
        float* o = out + warp * N_QUBITS;
#pragma unroll
        for (int q = 0; q < N_QUBITS; q++) o[q] = zv[q];
    }
}

extern "C" void kernel_launch(void* const* d_in, const int* in_sizes, int n_in,
                              void* d_out, int out_size) {
    const float* x  = (const float*)d_in[0];  // [16384, 10]
    const float* qw = (const float*)d_in[1];  // [2, 10, 3]
    float* out = (float*)d_out;               // [16384, 10]

    precompute_rot_kernel<<<1, 32>>>(qw);

    const int threads = 128;                      // 4 warps/block, 5 blocks/SM
    const int blocks  = (BATCH * 32) / threads;   // 4096
    sim_kernel<<<blocks, threads>>>(x, out);
}

// round 10
// speedup vs baseline: 1.0625x; 1.0025x over previous
#include <cuda_runtime.h>
#include <cuda_bf16.h>

// 10-qubit, batch-16384 circuit: RY embedding + 2x StronglyEntanglingLayers.
// R9 = R7 with launch config tuned to the no-spill point: 128 thr x 5 blk/SM
// (reg cap 102 >= ~95 natural demand, 20 warps/SM). Compact 4-scalar Rot
// coefficients, WHT epilogue, GF(2)-relabeled CNOTs, packed f32x2 math.

#define N_QUBITS 10
#define BATCH    16384

using ull = unsigned long long;

// ---------------- constexpr GF(2) relabeling ----------------
struct M10 { unsigned r[10]; };

__host__ __device__ constexpr M10 mident() {
    M10 m{}; for (int b = 0; b < 10; b++) m.r[b] = 1u << b; return m;
}
__host__ __device__ constexpr M10 mring(M10 m, int rr) {
    for (int q = 0; q < 10; q++) {
        int t = (q + rr) % 10;
        m.r[9 - t] ^= m.r[9 - q];
    }
    return m;
}
__host__ __device__ constexpr M10 minv(M10 a) {
    M10 inv = mident();
    for (int col = 0; col < 10; col++) {
        int piv = col;
        while (!((a.r[piv] >> col) & 1)) piv++;
        unsigned t = a.r[col]; a.r[col] = a.r[piv]; a.r[piv] = t;
        t = inv.r[col]; inv.r[col] = inv.r[piv]; inv.r[piv] = t;
        for (int r2 = 0; r2 < 10; r2++)
            if (r2 != col && ((a.r[r2] >> col) & 1)) { a.r[r2] ^= a.r[col]; inv.r[r2] ^= inv.r[col]; }
    }
    return inv;
}
__host__ __device__ constexpr unsigned mcol(M10 n, int b) {
    unsigned w = 0;
    for (int sb = 0; sb < 10; sb++) if ((n.r[sb] >> b) & 1) w |= 1u << sb;
    return w;
}
__host__ __device__ constexpr unsigned hibit(unsigned x) {
    unsigned b = 1; while (x >> 1) { x >>= 1; b <<= 1; } return b;
}

constexpr M10 kM1 = mring(mident(), 1);
constexpr M10 kN1 = minv(kM1);
constexpr M10 kM2 = mring(kM1, 2);

// ---------------- packed f32x2 primitives ----------------
__device__ __forceinline__ ull pk2(float lo, float hi) {
    ull u; asm("mov.b64 %0, {%1, %2};" : "=l"(u) : "f"(lo), "f"(hi)); return u;
}
__device__ __forceinline__ void un2(ull u, float& a, float& b) {
    asm("mov.b64 {%0, %1}, %2;" : "=f"(a), "=f"(b) : "l"(u));
}
__device__ __forceinline__ ull fma2(ull a, ull b, ull c) {
    ull d; asm("fma.rn.f32x2 %0, %1, %2, %3;" : "=l"(d) : "l"(a), "l"(b), "l"(c)); return d;
}
__device__ __forceinline__ ull mul2(ull a, ull b) {
    ull d; asm("mul.rn.f32x2 %0, %1, %2;" : "=l"(d) : "l"(a), "l"(b)); return d;
}
__device__ __forceinline__ ull add2(ull a, ull b) {
    ull d; asm("add.rn.f32x2 %0, %1, %2;" : "=l"(d) : "l"(a), "l"(b)); return d;
}
__device__ __forceinline__ ull shfl64x(ull v, int m) {
    float a, b; un2(v, a, b);
    a = __shfl_xor_sync(0xFFFFFFFFu, a, m);
    b = __shfl_xor_sync(0xFFFFFFFFu, b, m);
    return pk2(a, b);
}
__device__ __forceinline__ ull swap2(ull v) {
    float a, b; un2(v, a, b); return pk2(b, a);
}

// ---------------- precomputed compact Rot coefficients ----------------
// Rot = [[P - iQ, -R - iS], [R - iS, P + iQ]] with
// P=cos((phi+omega)/2)cos(th/2), Q=sin((phi+omega)/2)cos(th/2),
// R=cos((phi-omega)/2)sin(th/2), S=sin((phi-omega)/2)sin(th/2).
__device__ float4 g_rotc[2 * N_QUBITS];

__global__ void precompute_rot_kernel(const float* __restrict__ qw) {
    int i = threadIdx.x;
    if (i < 2 * N_QUBITS) {
        float phi = qw[i * 3 + 0], theta = qw[i * 3 + 1], omega = qw[i * 3 + 2];
        float st, ct;   sincosf(0.5f * theta, &st, &ct);
        float spo, cpo; sincosf(0.5f * (phi + omega), &spo, &cpo);
        float smo, cmo; sincosf(0.5f * (phi - omega), &smo, &cmo);
        g_rotc[i] = make_float4(cpo * ct, spo * ct, cmo * st, smo * st);
    }
}

// ---------------- generalized single-qubit gate ----------------
// Pairs stored s with s^W; role parity(s & R) selects matrix row.
// Update with sigma = +1 (role0) / -1 (role1):
//   re' = P*ar + S*oi + sigma*(Q*ai - R*or)
//   im' = P*ai - S*or + sigma*(-Q*ar - R*oi)
template <unsigned W, unsigned R>
__device__ __forceinline__ void gate(ull* rr, ull* ii, int lane, float4 m) {
    constexpr unsigned wl = W & 31u;
    constexpr unsigned wh = (W >> 5) & 31u;
    constexpr unsigned rl = R & 31u;
    constexpr unsigned rh = (R >> 5) & 31u;
    constexpr unsigned pw = wl >> 1;
    constexpr unsigned pr = rl >> 1;
    constexpr bool xh  = (wl & 1u) != 0;
    constexpr bool rhd = (rl & 1u) != 0;

    const unsigned lane_par = (0x96696996u >> (lane & rh)) & 1u;
    const float sp = lane_par ? -1.0f : 1.0f;      // sigma for half-lo, parity0
    const float sh = rhd ? -sp : sp;               // sigma for half-hi, parity0

    const ull P2  = pk2(m.x, m.x);
    const ull Sv2 = pk2(m.w, m.w);
    const ull nS2 = pk2(-m.w, -m.w);
    const ull QA  = pk2(sp * m.y, sh * m.y);
    const ull nQA = pk2(-sp * m.y, -sh * m.y);
    const ull RA  = pk2(sp * m.z, sh * m.z);
    const ull nRA = pk2(-sp * m.z, -sh * m.z);

#define CUPD(nre, nim, are, aie, ore, oie, PAR)                       \
    {                                                                 \
        ull Qp_ = (PAR) ? nQA : QA;                                   \
        ull Qm_ = (PAR) ? QA : nQA;                                   \
        ull Rp_ = (PAR) ? RA : nRA;                                   \
        ull t1_ = fma2(Qp_, (aie), mul2(Rp_, (ore)));                 \
        ull t2_ = fma2(Qm_, (are), mul2(Rp_, (oie)));                 \
        (nre) = fma2(P2, (are), fma2(Sv2, (oie), t1_));               \
        (nim) = fma2(P2, (aie), fma2(nS2, (ore), t2_));               \
    }

    if constexpr (pw == 0) {
#pragma unroll
        for (int p = 0; p < 16; p++) {
            ull ore = rr[p], oie = ii[p];
            if constexpr (wh != 0) { ore = shfl64x(ore, (int)wh); oie = shfl64x(oie, (int)wh); }
            if constexpr (xh)      { ore = swap2(ore); oie = swap2(oie); }
            const bool PAR = ((0x6996u >> (p & pr)) & 1u) != 0;
            ull nre, nim;
            CUPD(nre, nim, rr[p], ii[p], ore, oie, PAR);
            rr[p] = nre; ii[p] = nim;
        }
    } else {
        constexpr unsigned selbit = hibit(pw);
#pragma unroll
        for (int p = 0; p < 16; p++) {
            if (p & (int)selbit) continue;
            const int p2 = p ^ (int)pw;
            ull oa_re = rr[p2], oa_ie = ii[p2];
            ull ob_re = rr[p],  ob_ie = ii[p];
            if constexpr (wh != 0) {
                oa_re = shfl64x(oa_re, (int)wh); oa_ie = shfl64x(oa_ie, (int)wh);
                ob_re = shfl64x(ob_re, (int)wh); ob_ie = shfl64x(ob_ie, (int)wh);
            }
            if constexpr (xh) {
                oa_re = swap2(oa_re); oa_ie = swap2(oa_ie);
                ob_re = swap2(ob_re); ob_ie = swap2(ob_ie);
            }
            const bool pA = ((0x6996u >> (p  & pr)) & 1u) != 0;
            const bool pC = ((0x6996u >> (p2 & pr)) & 1u) != 0;
            ull nre1, nim1, nre2, nim2;
            CUPD(nre1, nim1, rr[p],  ii[p],  oa_re, oa_ie, pA);
            CUPD(nre2, nim2, rr[p2], ii[p2], ob_re, ob_ie, pC);
            rr[p] = nre1; ii[p] = nim1; rr[p2] = nre2; ii[p2] = nim2;
        }
    }
#undef CUPD
}

template <int Q>
__device__ __forceinline__ void apply_l1(ull* rr, ull* ii, int lane) {
    constexpr int b = 9 - Q;
    constexpr unsigned W = mcol(kN1, b);
    constexpr unsigned R = kM1.r[b];
    float4 m = __ldg(&g_rotc[N_QUBITS + Q]);
    gate<W, R>(rr, ii, lane, m);
}

// <Z_wireQ> from WHT array (compile-time mask extraction; kM2 not ODR-used).
template <int Q>
__device__ __forceinline__ float expz_wht(const ull* pp, int lane) {
    constexpr unsigned mr = kM2.r[9 - Q];
    constexpr unsigned rl = mr & 31u;
    constexpr unsigned rh = (mr >> 5) & 31u;
    constexpr unsigned ps = rl >> 1;
    float a, b; un2(pp[ps], a, b);
    float z = (rl & 1u) ? (a - b) : (a + b);
    if ((0x96696996u >> (lane & rh)) & 1u) z = -z;
    return z;
}

__device__ __forceinline__ float2 cmul(float2 a, float2 b) {
    return make_float2(a.x * b.x - a.y * b.y, a.x * b.y + a.y * b.x);
}

// ---------------- main kernel ----------------
__global__ void __launch_bounds__(128, 5)
sim_kernel(const float* __restrict__ x, float* __restrict__ out) {
    const int warp = (blockIdx.x * blockDim.x + threadIdx.x) >> 5;
    const int lane = threadIdx.x & 31;
    if (warp >= BATCH) return;

    const float* xs = x + warp * N_QUBITS;

    // ---- Prologue: per-wire factors after RY(x_q) then Rot(l=0,q) ----
    // f0 = (P c - R s, -(Q c + S s)); f1 = (R c + P s, Q s - S c)
    // Wires 0..4 are lane bits (lane bit j <-> wire 4-j): fold immediately.
    float2 lf = make_float2(1.0f, 0.0f);
#pragma unroll
    for (int j = 0; j < 5; j++) {
        const int q = 4 - j;
        float s, c; sincosf(0.5f * __ldg(&xs[q]), &s, &c);
        float4 m = __ldg(&g_rotc[q]);
        float2 f;
        if ((lane >> j) & 1)
            f = make_float2(fmaf(m.z, c, m.x * s), fmaf(m.y, s, -m.w * c));
        else
            f = make_float2(fmaf(m.x, c, -m.z * s), -fmaf(m.y, c, m.w * s));
        lf = cmul(lf, f);
    }

    // Wires 5..9 are local bits (stored bit j <-> wire 9-j; pack half = wire 9).
    float2 f0[5], f1[5];  // index j: wire 9-j
#pragma unroll
    for (int j = 0; j < 5; j++) {
        const int q = 9 - j;
        float s, c; sincosf(0.5f * __ldg(&xs[q]), &s, &c);
        float4 m = __ldg(&g_rotc[q]);
        f0[j] = make_float2(fmaf(m.x, c, -m.z * s), -fmaf(m.y, c, m.w * s));
        f1[j] = make_float2(fmaf(m.z, c, m.x * s), fmaf(m.y, s, -m.w * c));
    }

    // Local product tree over pack-half (wire 9) and p bits (wires 8..5).
    ull rr[16], ii[16];
    {
        float2 a0 = cmul(f0[0], lf);
        float2 a1 = cmul(f1[0], lf);
        rr[0] = pk2(a0.x, a1.x); ii[0] = pk2(a0.y, a1.y);
    }
#pragma unroll
    for (int j = 1; j < 5; j++) {
        const int n = 1 << (j - 1);
        float2 w0 = f0[j], w1 = f1[j];
        ull w0re = pk2(w0.x, w0.x), w0im = pk2(w0.y, w0.y), w0mn = pk2(-w0.y, -w0.y);
        ull w1re = pk2(w1.x, w1.x), w1im = pk2(w1.y, w1.y), w1mn = pk2(-w1.y, -w1.y);
#pragma unroll
        for (int p = 0; p < n; p++) {
            ull zr = rr[p], zi = ii[p];
            rr[p | n] = fma2(w1re, zr, mul2(w1mn, zi));
            ii[p | n] = fma2(w1re, zi, mul2(w1im, zr));
            rr[p]     = fma2(w0re, zr, mul2(w0mn, zi));
            ii[p]     = fma2(w0re, zi, mul2(w0im, zr));
        }
    }
    // State == embedding + layer0 Rots; layer0 CNOT ring absorbed into masks.

    // ---- Layer-1 Rot gates in relabeled basis ----
    apply_l1<0>(rr, ii, lane);
    apply_l1<1>(rr, ii, lane);
    apply_l1<2>(rr, ii, lane);
    apply_l1<3>(rr, ii, lane);
    apply_l1<4>(rr, ii, lane);
    apply_l1<5>(rr, ii, lane);
    apply_l1<6>(rr, ii, lane);
    apply_l1<7>(rr, ii, lane);
    apply_l1<8>(rr, ii, lane);
    apply_l1<9>(rr, ii, lane);
    // Layer-1 CNOT ring absorbed into measurement masks (kM2).

    // ---- Probabilities + Walsh-Hadamard over the 4 p-bits ----
    ull pp[16];
#pragma unroll
    for (int p = 0; p < 16; p++) pp[p] = fma2(rr[p], rr[p], mul2(ii[p], ii[p]));

    const ull kNeg1 = pk2(-1.0f, -1.0f);
#pragma unroll
    for (int b = 1; b < 16; b <<= 1) {
#pragma unroll
        for (int p = 0; p < 16; p++) {
            if (p & b) continue;
            ull u = pp[p], v = pp[p | b];
            pp[p]     = add2(u, v);
            pp[p | b] = fma2(v, kNeg1, u);  // u - v
        }
    }
    // pp[mask] = sum_p (-1)^{parity(p & mask)} |amp|^2 (packed per half)

    float zv[10];
    zv[0] = expz_wht<0>(pp, lane);
    zv[1] = expz_wht<1>(pp, lane);
    zv[2] = expz_wht<2>(pp, lane);
    zv[3] = expz_wht<3>(pp, lane);
    zv[4] = expz_wht<4>(pp, lane);
    zv[5] = expz_wht<5>(pp, lane);
    zv[6] = expz_wht<6>(pp, lane);
    zv[7] = expz_wht<7>(pp, lane);
    zv[8] = expz_wht<8>(pp, lane);
    zv[9] = expz_wht<9>(pp, lane);

#pragma unroll
    for (int off = 16; off > 0; off >>= 1) {
#pragma unroll
        for (int q = 0; q < 10; q++)
            zv[q] += __shfl_xor_sync(0xFFFFFFFFu, zv[q], off);
    }

    if (lane == 0) {
        float* o = out + warp * N_QUBITS;
#pragma unroll
        for (int q = 0; q < N_QUBITS; q++) o[q] = zv[q];
    }
}

extern "C" void kernel_launch(void* const* d_in, const int* in_sizes, int n_in,
                              void* d_out, int out_size) {
    const float* x  = (const float*)d_in[0];  // [16384, 10]
    const float* qw = (const float*)d_in[1];  // [2, 10, 3]
    float* out = (float*)d_out;               // [16384, 10]

    precompute_rot_kernel<<<1, 32>>>(qw);

    const int threads = 128;                      // 4 warps/block, 5 blocks/SM
    const int blocks  = (BATCH * 32) / threads;   // 4096
    sim_kernel<<<blocks, threads>>>(x, out);
}

// round 11
// speedup vs baseline: 1.0668x; 1.0040x over previous
#include <cuda_runtime.h>
#include <cuda_bf16.h>

// 10-qubit, batch-16384 circuit: RY embedding + 2x StronglyEntanglingLayers.
// R11 = R9 + (a) 12-SHFL split-tree epilogue, (b) __sincosf fast trig,
// (c) 96thr x 7blk/SM (21 warps, reg cap 96 = natural demand, no spill).
// CNOTs eliminated via GF(2) relabeling; packed f32x2 complex math.

#define N_QUBITS 10
#define BATCH    16384

using ull = unsigned long long;

// ---------------- constexpr GF(2) relabeling ----------------
struct M10 { unsigned r[10]; };

__host__ __device__ constexpr M10 mident() {
    M10 m{}; for (int b = 0; b < 10; b++) m.r[b] = 1u << b; return m;
}
__host__ __device__ constexpr M10 mring(M10 m, int rr) {
    for (int q = 0; q < 10; q++) {
        int t = (q + rr) % 10;
        m.r[9 - t] ^= m.r[9 - q];
    }
    return m;
}
__host__ __device__ constexpr M10 minv(M10 a) {
    M10 inv = mident();
    for (int col = 0; col < 10; col++) {
        int piv = col;
        while (!((a.r[piv] >> col) & 1)) piv++;
        unsigned t = a.r[col]; a.r[col] = a.r[piv]; a.r[piv] = t;
        t = inv.r[col]; inv.r[col] = inv.r[piv]; inv.r[piv] = t;
        for (int r2 = 0; r2 < 10; r2++)
            if (r2 != col && ((a.r[r2] >> col) & 1)) { a.r[r2] ^= a.r[col]; inv.r[r2] ^= inv.r[col]; }
    }
    return inv;
}
__host__ __device__ constexpr unsigned mcol(M10 n, int b) {
    unsigned w = 0;
    for (int sb = 0; sb < 10; sb++) if ((n.r[sb] >> b) & 1) w |= 1u << sb;
    return w;
}
__host__ __device__ constexpr unsigned hibit(unsigned x) {
    unsigned b = 1; while (x >> 1) { x >>= 1; b <<= 1; } return b;
}

constexpr M10 kM1 = mring(mident(), 1);
constexpr M10 kN1 = minv(kM1);
constexpr M10 kM2 = mring(kM1, 2);

// ---------------- packed f32x2 primitives ----------------
__device__ __forceinline__ ull pk2(float lo, float hi) {
    ull u; asm("mov.b64 %0, {%1, %2};" : "=l"(u) : "f"(lo), "f"(hi)); return u;
}
__device__ __forceinline__ void un2(ull u, float& a, float& b) {
    asm("mov.b64 {%0, %1}, %2;" : "=f"(a), "=f"(b) : "l"(u));
}
__device__ __forceinline__ ull fma2(ull a, ull b, ull c) {
    ull d; asm("fma.rn.f32x2 %0, %1, %2, %3;" : "=l"(d) : "l"(a), "l"(b), "l"(c)); return d;
}
__device__ __forceinline__ ull mul2(ull a, ull b) {
    ull d; asm("mul.rn.f32x2 %0, %1, %2;" : "=l"(d) : "l"(a), "l"(b)); return d;
}
__device__ __forceinline__ ull add2(ull a, ull b) {
    ull d; asm("add.rn.f32x2 %0, %1, %2;" : "=l"(d) : "l"(a), "l"(b)); return d;
}
__device__ __forceinline__ ull shfl64x(ull v, int m) {
    float a, b; un2(v, a, b);
    a = __shfl_xor_sync(0xFFFFFFFFu, a, m);
    b = __shfl_xor_sync(0xFFFFFFFFu, b, m);
    return pk2(a, b);
}
__device__ __forceinline__ ull swap2(ull v) {
    float a, b; un2(v, a, b); return pk2(b, a);
}

// ---------------- precomputed compact Rot coefficients ----------------
// Rot = [[P - iQ, -R - iS], [R - iS, P + iQ]] with
// P=cos((phi+omega)/2)cos(th/2), Q=sin((phi+omega)/2)cos(th/2),
// R=cos((phi-omega)/2)sin(th/2), S=sin((phi-omega)/2)sin(th/2).
__device__ float4 g_rotc[2 * N_QUBITS];

__global__ void precompute_rot_kernel(const float* __restrict__ qw) {
    int i = threadIdx.x;
    if (i < 2 * N_QUBITS) {
        float phi = qw[i * 3 + 0], theta = qw[i * 3 + 1], omega = qw[i * 3 + 2];
        float st, ct;   sincosf(0.5f * theta, &st, &ct);
        float spo, cpo; sincosf(0.5f * (phi + omega), &spo, &cpo);
        float smo, cmo; sincosf(0.5f * (phi - omega), &smo, &cmo);
        g_rotc[i] = make_float4(cpo * ct, spo * ct, cmo * st, smo * st);
    }
}

// ---------------- generalized single-qubit gate ----------------
// Pairs stored s with s^W; role parity(s & R) selects matrix row.
template <unsigned W, unsigned R>
__device__ __forceinline__ void gate(ull* rr, ull* ii, int lane, float4 m) {
    constexpr unsigned wl = W & 31u;
    constexpr unsigned wh = (W >> 5) & 31u;
    constexpr unsigned rl = R & 31u;
    constexpr unsigned rh = (R >> 5) & 31u;
    constexpr unsigned pw = wl >> 1;
    constexpr unsigned pr = rl >> 1;
    constexpr bool xh  = (wl & 1u) != 0;
    constexpr bool rhd = (rl & 1u) != 0;

    const unsigned lane_par = (0x96696996u >> (lane & rh)) & 1u;
    const float sp = lane_par ? -1.0f : 1.0f;      // sigma for half-lo, parity0
    const float sh = rhd ? -sp : sp;               // sigma for half-hi, parity0

    const ull P2  = pk2(m.x, m.x);
    const ull Sv2 = pk2(m.w, m.w);
    const ull nS2 = pk2(-m.w, -m.w);
    const ull QA  = pk2(sp * m.y, sh * m.y);
    const ull nQA = pk2(-sp * m.y, -sh * m.y);
    const ull RA  = pk2(sp * m.z, sh * m.z);
    const ull nRA = pk2(-sp * m.z, -sh * m.z);

#define CUPD(nre, nim, are, aie, ore, oie, PAR)                       \
    {                                                                 \
        ull Qp_ = (PAR) ? nQA : QA;                                   \
        ull Qm_ = (PAR) ? QA : nQA;                                   \
        ull Rp_ = (PAR) ? RA : nRA;                                   \
        ull t1_ = fma2(Qp_, (aie), mul2(Rp_, (ore)));                 \
        ull t2_ = fma2(Qm_, (are), mul2(Rp_, (oie)));                 \
        (nre) = fma2(P2, (are), fma2(Sv2, (oie), t1_));               \
        (nim) = fma2(P2, (aie), fma2(nS2, (ore), t2_));               \
    }

    if constexpr (pw == 0) {
#pragma unroll
        for (int p = 0; p < 16; p++) {
            ull ore = rr[p], oie = ii[p];
            if constexpr (wh != 0) { ore = shfl64x(ore, (int)wh); oie = shfl64x(oie, (int)wh); }
            if constexpr (xh)      { ore = swap2(ore); oie = swap2(oie); }
            const bool PAR = ((0x6996u >> (p & pr)) & 1u) != 0;
            ull nre, nim;
            CUPD(nre, nim, rr[p], ii[p], ore, oie, PAR);
            rr[p] = nre; ii[p] = nim;
        }
    } else {
        constexpr unsigned selbit = hibit(pw);
#pragma unroll
        for (int p = 0; p < 16; p++) {
            if (p & (int)selbit) continue;
            const int p2 = p ^ (int)pw;
            ull oa_re = rr[p2], oa_ie = ii[p2];
            ull ob_re = rr[p],  ob_ie = ii[p];
            if constexpr (wh != 0) {
                oa_re = shfl64x(oa_re, (int)wh); oa_ie = shfl64x(oa_ie, (int)wh);
                ob_re = shfl64x(ob_re, (int)wh); ob_ie = shfl64x(ob_ie, (int)wh);
            }
            if constexpr (xh) {
                oa_re = swap2(oa_re); oa_ie = swap2(oa_ie);
                ob_re = swap2(ob_re); ob_ie = swap2(ob_ie);
            }
            const bool pA = ((0x6996u >> (p  & pr)) & 1u) != 0;
            const bool pC = ((0x6996u >> (p2 & pr)) & 1u) != 0;
            ull nre1, nim1, nre2, nim2;
            CUPD(nre1, nim1, rr[p],  ii[p],  oa_re, oa_ie, pA);
            CUPD(nre2, nim2, rr[p2], ii[p2], ob_re, ob_ie, pC);
            rr[p] = nre1; ii[p] = nim1; rr[p2] = nre2; ii[p2] = nim2;
        }
    }
#undef CUPD
}

template <int Q>
__device__ __forceinline__ void apply_l1(ull* rr, ull* ii, int lane) {
    constexpr int b = 9 - Q;
    constexpr unsigned W = mcol(kN1, b);
    constexpr unsigned R = kM1.r[b];
    float4 m = __ldg(&g_rotc[N_QUBITS + Q]);
    gate<W, R>(rr, ii, lane, m);
}

// <Z_wireQ> from WHT array (compile-time mask extraction).
template <int Q>
__device__ __forceinline__ float expz_wht(const ull* pp, int lane) {
    constexpr unsigned mr = kM2.r[9 - Q];
    constexpr unsigned rl = mr & 31u;
    constexpr unsigned rh = (mr >> 5) & 31u;
    constexpr unsigned ps = rl >> 1;
    float a, b; un2(pp[ps], a, b);
    float z = (rl & 1u) ? (a - b) : (a + b);
    if ((0x96696996u >> (lane & rh)) & 1u) z = -z;
    return z;
}

__device__ __forceinline__ float2 cmul(float2 a, float2 b) {
    return make_float2(a.x * b.x - a.y * b.y, a.x * b.y + a.y * b.x);
}

// ---------------- main kernel ----------------
__global__ void __launch_bounds__(96, 7)
sim_kernel(const float* __restrict__ x, float* __restrict__ out) {
    const int warp = (blockIdx.x * blockDim.x + threadIdx.x) >> 5;
    const int lane = threadIdx.x & 31;
    if (warp >= BATCH) return;

    const float* xs = x + warp * N_QUBITS;

    // ---- Prologue: per-wire factors after RY(x_q) then Rot(l=0,q) ----
    // f0 = (P c - R s, -(Q c + S s)); f1 = (R c + P s, Q s - S c)
    float2 lf = make_float2(1.0f, 0.0f);
#pragma unroll
    for (int j = 0; j < 5; j++) {
        const int q = 4 - j;
        float s, c; __sincosf(0.5f * __ldg(&xs[q]), &s, &c);
        float4 m = __ldg(&g_rotc[q]);
        float2 f;
        if ((lane >> j) & 1)
            f = make_float2(fmaf(m.z, c, m.x * s), fmaf(m.y, s, -m.w * c));
        else
            f = make_float2(fmaf(m.x, c, -m.z * s), -fmaf(m.y, c, m.w * s));
        lf = cmul(lf, f);
    }

    float2 f0[5], f1[5];  // index j: wire 9-j
#pragma unroll
    for (int j = 0; j < 5; j++) {
        const int q = 9 - j;
        float s, c; __sincosf(0.5f * __ldg(&xs[q]), &s, &c);
        float4 m = __ldg(&g_rotc[q]);
        f0[j] = make_float2(fmaf(m.x, c, -m.z * s), -fmaf(m.y, c, m.w * s));
        f1[j] = make_float2(fmaf(m.z, c, m.x * s), fmaf(m.y, s, -m.w * c));
    }

    // Local product tree over pack-half (wire 9) and p bits (wires 8..5).
    ull rr[16], ii[16];
    {
        float2 a0 = cmul(f0[0], lf);
        float2 a1 = cmul(f1[0], lf);
        rr[0] = pk2(a0.x, a1.x); ii[0] = pk2(a0.y, a1.y);
    }
#pragma unroll
    for (int j = 1; j < 5; j++) {
        const int n = 1 << (j - 1);
        float2 w0 = f0[j], w1 = f1[j];
        ull w0re = pk2(w0.x, w0.x), w0im = pk2(w0.y, w0.y), w0mn = pk2(-w0.y, -w0.y);
        ull w1re = pk2(w1.x, w1.x), w1im = pk2(w1.y, w1.y), w1mn = pk2(-w1.y, -w1.y);
#pragma unroll
        for (int p = 0; p < n; p++) {
            ull zr = rr[p], zi = ii[p];
            rr[p | n] = fma2(w1re, zr, mul2(w1mn, zi));
            ii[p | n] = fma2(w1re, zi, mul2(w1im, zr));
            rr[p]     = fma2(w0re, zr, mul2(w0mn, zi));
            ii[p]     = fma2(w0re, zi, mul2(w0im, zr));
        }
    }
    // State == embedding + layer0 Rots; layer0 CNOT ring absorbed into masks.

    // ---- Layer-1 Rot gates in relabeled basis ----
    apply_l1<0>(rr, ii, lane);
    apply_l1<1>(rr, ii, lane);
    apply_l1<2>(rr, ii, lane);
    apply_l1<3>(rr, ii, lane);
    apply_l1<4>(rr, ii, lane);
    apply_l1<5>(rr, ii, lane);
    apply_l1<6>(rr, ii, lane);
    apply_l1<7>(rr, ii, lane);
    apply_l1<8>(rr, ii, lane);
    apply_l1<9>(rr, ii, lane);
    // Layer-1 CNOT ring absorbed into measurement masks (kM2).

    // ---- Probabilities + Walsh-Hadamard over the 4 p-bits ----
    ull pp[16];
#pragma unroll
    for (int p = 0; p < 16; p++) pp[p] = fma2(rr[p], rr[p], mul2(ii[p], ii[p]));

    const ull kNeg1 = pk2(-1.0f, -1.0f);
#pragma unroll
    for (int b = 1; b < 16; b <<= 1) {
#pragma unroll
        for (int p = 0; p < 16; p++) {
            if (p & b) continue;
            ull u = pp[p], v = pp[p | b];
            pp[p]     = add2(u, v);
            pp[p | b] = fma2(v, kNeg1, u);  // u - v
        }
    }

    float zv[10];
    zv[0] = expz_wht<0>(pp, lane);
    zv[1] = expz_wht<1>(pp, lane);
    zv[2] = expz_wht<2>(pp, lane);
    zv[3] = expz_wht<3>(pp, lane);
    zv[4] = expz_wht<4>(pp, lane);
    zv[5] = expz_wht<5>(pp, lane);
    zv[6] = expz_wht<6>(pp, lane);
    zv[7] = expz_wht<7>(pp, lane);
    zv[8] = expz_wht<8>(pp, lane);
    zv[9] = expz_wht<9>(pp, lane);

    // ---- split-tree warp reduction: 12 SHFLs for all 10 sums ----
    const bool b4 = (lane & 16) != 0;
    const bool b3 = (lane & 8) != 0;
    const bool b2 = (lane & 4) != 0;
    const bool b1 = (lane & 2) != 0;
    const bool b0 = (lane & 1) != 0;

    // step 1 (xor 16): b4=0 lanes own arrays 0..4, b4=1 own 5..9
    float acc0, acc1, acc2, acc3, acc4;
    {
        float s, r;
        s = b4 ? zv[0] : zv[5]; r = __shfl_xor_sync(0xFFFFFFFFu, s, 16);
        acc0 = (b4 ? zv[5] : zv[0]) + r;
        s = b4 ? zv[1] : zv[6]; r = __shfl_xor_sync(0xFFFFFFFFu, s, 16);
        acc1 = (b4 ? zv[6] : zv[1]) + r;
        s = b4 ? zv[2] : zv[7]; r = __shfl_xor_sync(0xFFFFFFFFu, s, 16);
        acc2 = (b4 ? zv[7] : zv[2]) + r;
        s = b4 ? zv[3] : zv[8]; r = __shfl_xor_sync(0xFFFFFFFFu, s, 16);
        acc3 = (b4 ? zv[8] : zv[3]) + r;
        s = b4 ? zv[4] : zv[9]; r = __shfl_xor_sync(0xFFFFFFFFu, s, 16);
        acc4 = (b4 ? zv[9] : zv[4]) + r;
    }

    // step 2 (xor 8): b3=0 keeps {acc0,acc1,acc2}, b3=1 keeps {acc3,acc4}
    float c0, c1, c2;
    {
        float s0 = b3 ? acc0 : acc3;
        float s1 = b3 ? acc1 : acc4;
        float s2 = acc2;  // payload used only from b3=1 side
        float r0 = __shfl_xor_sync(0xFFFFFFFFu, s0, 8);
        float r1 = __shfl_xor_sync(0xFFFFFFFFu, s1, 8);
        float r2 = __shfl_xor_sync(0xFFFFFFFFu, s2, 8);
        c0 = (b3 ? acc3 : acc0) + r0;
        c1 = (b3 ? acc4 : acc1) + r1;
        c2 = b3 ? 0.0f : (acc2 + r2);
    }

    // step 3 (xor 4):
    //  b3=0: b2=0 keeps {c0,c1}; b2=1 keeps {c2}
    //  b3=1: b2=0 keeps {c0};    b2=1 keeps {c1}
    float d0, d1;
    {
        float s0 = b3 ? (b2 ? c0 : c1) : (b2 ? c0 : c2);
        float s1 = c1;  // used only by (b3=0, b2=0) receivers, sent from b2=1 side
        float r0 = __shfl_xor_sync(0xFFFFFFFFu, s0, 4);
        float r1 = __shfl_xor_sync(0xFFFFFFFFu, s1, 4);
        float own = b3 ? (b2 ? c1 : c0) : (b2 ? c2 : c0);
        d0 = own + r0;
        d1 = (!b3 && !b2) ? (c1 + r1) : 0.0f;
    }

    // step 4 (xor 2): only (b3=0,b2=0) lanes still hold 2 arrays
    float e;
    {
        const bool two = (!b3 && !b2);
        float s = two ? (b1 ? d0 : d1) : d0;
        float r = __shfl_xor_sync(0xFFFFFFFFu, s, 2);
        float own = two ? (b1 ? d1 : d0) : d0;
        e = own + r;
    }

    // step 5 (xor 1)
    e += __shfl_xor_sync(0xFFFFFFFFu, e, 1);

    // each lane owns exactly one array; canonical lane writes it
    {
        const int pos = b3 ? (b2 ? 4 : 3) : (b2 ? 2 : (b1 ? 1 : 0));
        const int q = (b4 ? 5 : 0) + pos;
        const bool canon = !b0 && (pos >= 2 ? !b1 : true);
        if (canon) out[warp * N_QUBITS + q] = e;
    }
}

extern "C" void kernel_launch(void* const* d_in, const int* in_sizes, int n_in,
                              void* d_out, int out_size) {
    const float* x  = (const float*)d_in[0];  // [16384, 10]
    const float* qw = (const float*)d_in[1];  // [2, 10, 3]
    float* out = (float*)d_out;               // [16384, 10]

    precompute_rot_kernel<<<1, 32>>>(qw);

    const int threads = 96;                              // 3 warps/block, 7 blocks/SM
    const int blocks  = (BATCH * 32 + threads - 1) / threads;  // 5462
    sim_kernel<<<blocks, threads>>>(x, out);
}

// round 12
// speedup vs baseline: 1.1349x; 1.0638x over previous
#include <cuda_runtime.h>
#include <cuda_bf16.h>

// 10-qubit, batch-16384 circuit: RY embedding + 2x StronglyEntanglingLayers.
// R12 = R10 launch config (128thr x 5blk/SM, no spill) + R11 improvements
// (12-SHFL split-tree epilogue, __sincosf). GF(2)-relabeled CNOTs, compact
// 4-scalar Rot coefficients, WHT measurement, packed f32x2 complex math.

#define N_QUBITS 10
#define BATCH    16384

using ull = unsigned long long;

// ---------------- constexpr GF(2) relabeling ----------------
struct M10 { unsigned r[10]; };

__host__ __device__ constexpr M10 mident() {
    M10 m{}; for (int b = 0; b < 10; b++) m.r[b] = 1u << b; return m;
}
__host__ __device__ constexpr M10 mring(M10 m, int rr) {
    for (int q = 0; q < 10; q++) {
        int t = (q + rr) % 10;
        m.r[9 - t] ^= m.r[9 - q];
    }
    return m;
}
__host__ __device__ constexpr M10 minv(M10 a) {
    M10 inv = mident();
    for (int col = 0; col < 10; col++) {
        int piv = col;
        while (!((a.r[piv] >> col) & 1)) piv++;
        unsigned t = a.r[col]; a.r[col] = a.r[piv]; a.r[piv] = t;
        t = inv.r[col]; inv.r[col] = inv.r[piv]; inv.r[piv] = t;
        for (int r2 = 0; r2 < 10; r2++)
            if (r2 != col && ((a.r[r2] >> col) & 1)) { a.r[r2] ^= a.r[col]; inv.r[r2] ^= inv.r[col]; }
    }
    return inv;
}
__host__ __device__ constexpr unsigned mcol(M10 n, int b) {
    unsigned w = 0;
    for (int sb = 0; sb < 10; sb++) if ((n.r[sb] >> b) & 1) w |= 1u << sb;
    return w;
}
__host__ __device__ constexpr unsigned hibit(unsigned x) {
    unsigned b = 1; while (x >> 1) { x >>= 1; b <<= 1; } return b;
}

constexpr M10 kM1 = mring(mident(), 1);
constexpr M10 kN1 = minv(kM1);
constexpr M10 kM2 = mring(kM1, 2);

// ---------------- packed f32x2 primitives ----------------
__device__ __forceinline__ ull pk2(float lo, float hi) {
    ull u; asm("mov.b64 %0, {%1, %2};" : "=l"(u) : "f"(lo), "f"(hi)); return u;
}
__device__ __forceinline__ void un2(ull u, float& a, float& b) {
    asm("mov.b64 {%0, %1}, %2;" : "=f"(a), "=f"(b) : "l"(u));
}
__device__ __forceinline__ ull fma2(ull a, ull b, ull c) {
    ull d; asm("fma.rn.f32x2 %0, %1, %2, %3;" : "=l"(d) : "l"(a), "l"(b), "l"(c)); return d;
}
__device__ __forceinline__ ull mul2(ull a, ull b) {
    ull d; asm("mul.rn.f32x2 %0, %1, %2;" : "=l"(d) : "l"(a), "l"(b)); return d;
}
__device__ __forceinline__ ull add2(ull a, ull b) {
    ull d; asm("add.rn.f32x2 %0, %1, %2;" : "=l"(d) : "l"(a), "l"(b)); return d;
}
__device__ __forceinline__ ull shfl64x(ull v, int m) {
    float a, b; un2(v, a, b);
    a = __shfl_xor_sync(0xFFFFFFFFu, a, m);
    b = __shfl_xor_sync(0xFFFFFFFFu, b, m);
    return pk2(a, b);
}
__device__ __forceinline__ ull swap2(ull v) {
    float a, b; un2(v, a, b); return pk2(b, a);
}

// ---------------- precomputed compact Rot coefficients ----------------
// Rot = [[P - iQ, -R - iS], [R - iS, P + iQ]] with
// P=cos((phi+omega)/2)cos(th/2), Q=sin((phi+omega)/2)cos(th/2),
// R=cos((phi-omega)/2)sin(th/2), S=sin((phi-omega)/2)sin(th/2).
__device__ float4 g_rotc[2 * N_QUBITS];

__global__ void precompute_rot_kernel(const float* __restrict__ qw) {
    int i = threadIdx.x;
    if (i < 2 * N_QUBITS) {
        float phi = qw[i * 3 + 0], theta = qw[i * 3 + 1], omega = qw[i * 3 + 2];
        float st, ct;   sincosf(0.5f * theta, &st, &ct);
        float spo, cpo; sincosf(0.5f * (phi + omega), &spo, &cpo);
        float smo, cmo; sincosf(0.5f * (phi - omega), &smo, &cmo);
        g_rotc[i] = make_float4(cpo * ct, spo * ct, cmo * st, smo * st);
    }
}

// ---------------- generalized single-qubit gate ----------------
// Pairs stored s with s^W; role parity(s & R) selects matrix row.
template <unsigned W, unsigned R>
__device__ __forceinline__ void gate(ull* rr, ull* ii, int lane, float4 m) {
    constexpr unsigned wl = W & 31u;
    constexpr unsigned wh = (W >> 5) & 31u;
    constexpr unsigned rl = R & 31u;
    constexpr unsigned rh = (R >> 5) & 31u;
    constexpr unsigned pw = wl >> 1;
    constexpr unsigned pr = rl >> 1;
    constexpr bool xh  = (wl & 1u) != 0;
    constexpr bool rhd = (rl & 1u) != 0;

    const unsigned lane_par = (0x96696996u >> (lane & rh)) & 1u;
    const float sp = lane_par ? -1.0f : 1.0f;      // sigma for half-lo, parity0
    const float sh = rhd ? -sp : sp;               // sigma for half-hi, parity0

    const ull P2  = pk2(m.x, m.x);
    const ull Sv2 = pk2(m.w, m.w);
    const ull nS2 = pk2(-m.w, -m.w);
    const ull QA  = pk2(sp * m.y, sh * m.y);
    const ull nQA = pk2(-sp * m.y, -sh * m.y);
    const ull RA  = pk2(sp * m.z, sh * m.z);
    const ull nRA = pk2(-sp * m.z, -sh * m.z);

#define CUPD(nre, nim, are, aie, ore, oie, PAR)                       \
    {                                                                 \
        ull Qp_ = (PAR) ? nQA : QA;                                   \
        ull Qm_ = (PAR) ? QA : nQA;                                   \
        ull Rp_ = (PAR) ? RA : nRA;                                   \
        ull t1_ = fma2(Qp_, (aie), mul2(Rp_, (ore)));                 \
        ull t2_ = fma2(Qm_, (are), mul2(Rp_, (oie)));                 \
        (nre) = fma2(P2, (are), fma2(Sv2, (oie), t1_));               \
        (nim) = fma2(P2, (aie), fma2(nS2, (ore), t2_));               \
    }

    if constexpr (pw == 0) {
#pragma unroll
        for (int p = 0; p < 16; p++) {
            ull ore = rr[p], oie = ii[p];
            if constexpr (wh != 0) { ore = shfl64x(ore, (int)wh); oie = shfl64x(oie, (int)wh); }
            if constexpr (xh)      { ore = swap2(ore); oie = swap2(oie); }
            const bool PAR = ((0x6996u >> (p & pr)) & 1u) != 0;
            ull nre, nim;
            CUPD(nre, nim, rr[p], ii[p], ore, oie, PAR);
            rr[p] = nre; ii[p] = nim;
        }
    } else {
        constexpr unsigned selbit = hibit(pw);
#pragma unroll
        for (int p = 0; p < 16; p++) {
            if (p & (int)selbit) continue;
            const int p2 = p ^ (int)pw;
            ull oa_re = rr[p2], oa_ie = ii[p2];
            ull ob_re = rr[p],  ob_ie = ii[p];
            if constexpr (wh != 0) {
                oa_re = shfl64x(oa_re, (int)wh); oa_ie = shfl64x(oa_ie, (int)wh);
                ob_re = shfl64x(ob_re, (int)wh); ob_ie = shfl64x(ob_ie, (int)wh);
            }
            if constexpr (xh) {
                oa_re = swap2(oa_re); oa_ie = swap2(oa_ie);
                ob_re = swap2(ob_re); ob_ie = swap2(ob_ie);
            }
            const bool pA = ((0x6996u >> (p  & pr)) & 1u) != 0;
            const bool pC = ((0x6996u >> (p2 & pr)) & 1u) != 0;
            ull nre1, nim1, nre2, nim2;
            CUPD(nre1, nim1, rr[p],  ii[p],  oa_re, oa_ie, pA);
            CUPD(nre2, nim2, rr[p2], ii[p2], ob_re, ob_ie, pC);
            rr[p] = nre1; ii[p] = nim1; rr[p2] = nre2; ii[p2] = nim2;
        }
    }
#undef CUPD
}

template <int Q>
__device__ __forceinline__ void apply_l1(ull* rr, ull* ii, int lane) {
    constexpr int b = 9 - Q;
    constexpr unsigned W = mcol(kN1, b);
    constexpr unsigned R = kM1.r[b];
    float4 m = __ldg(&g_rotc[N_QUBITS + Q]);
    gate<W, R>(rr, ii, lane, m);
}

// <Z_wireQ> from WHT array (compile-time mask extraction).
template <int Q>
__device__ __forceinline__ float expz_wht(const ull* pp, int lane) {
    constexpr unsigned mr = kM2.r[9 - Q];
    constexpr unsigned rl = mr & 31u;
    constexpr unsigned rh = (mr >> 5) & 31u;
    constexpr unsigned ps = rl >> 1;
    float a, b; un2(pp[ps], a, b);
    float z = (rl & 1u) ? (a - b) : (a + b);
    if ((0x96696996u >> (lane & rh)) & 1u) z = -z;
    return z;
}

__device__ __forceinline__ float2 cmul(float2 a, float2 b) {
    return make_float2(a.x * b.x - a.y * b.y, a.x * b.y + a.y * b.x);
}

// ---------------- main kernel ----------------
__global__ void __launch_bounds__(128, 5)
sim_kernel(const float* __restrict__ x, float* __restrict__ out) {
    const int warp = (blockIdx.x * blockDim.x + threadIdx.x) >> 5;
    const int lane = threadIdx.x & 31;
    if (warp >= BATCH) return;

    const float* xs = x + warp * N_QUBITS;

    // ---- Prologue: per-wire factors after RY(x_q) then Rot(l=0,q) ----
    // f0 = (P c - R s, -(Q c + S s)); f1 = (R c + P s, Q s - S c)
    float2 lf = make_float2(1.0f, 0.0f);
#pragma unroll
    for (int j = 0; j < 5; j++) {
        const int q = 4 - j;
        float s, c; __sincosf(0.5f * __ldg(&xs[q]), &s, &c);
        float4 m = __ldg(&g_rotc[q]);
        float2 f;
        if ((lane >> j) & 1)
            f = make_float2(fmaf(m.z, c, m.x * s), fmaf(m.y, s, -m.w * c));
        else
            f = make_float2(fmaf(m.x, c, -m.z * s), -fmaf(m.y, c, m.w * s));
        lf = cmul(lf, f);
    }

    float2 f0[5], f1[5];  // index j: wire 9-j
#pragma unroll
    for (int j = 0; j < 5; j++) {
        const int q = 9 - j;
        float s, c; __sincosf(0.5f * __ldg(&xs[q]), &s, &c);
        float4 m = __ldg(&g_rotc[q]);
        f0[j] = make_float2(fmaf(m.x, c, -m.z * s), -fmaf(m.y, c, m.w * s));
        f1[j] = make_float2(fmaf(m.z, c, m.x * s), fmaf(m.y, s, -m.w * c));
    }

    // Local product tree over pack-half (wire 9) and p bits (wires 8..5).
    ull rr[16], ii[16];
    {
        float2 a0 = cmul(f0[0], lf);
        float2 a1 = cmul(f1[0], lf);
        rr[0] = pk2(a0.x, a1.x); ii[0] = pk2(a0.y, a1.y);
    }
#pragma unroll
    for (int j = 1; j < 5; j++) {
        const int n = 1 << (j - 1);
        float2 w0 = f0[j], w1 = f1[j];
        ull w0re = pk2(w0.x, w0.x), w0im = pk2(w0.y, w0.y), w0mn = pk2(-w0.y, -w0.y);
        ull w1re = pk2(w1.x, w1.x), w1im = pk2(w1.y, w1.y), w1mn = pk2(-w1.y, -w1.y);
#pragma unroll
        for (int p = 0; p < n; p++) {
            ull zr = rr[p], zi = ii[p];
            rr[p | n] = fma2(w1re, zr, mul2(w1mn, zi));
            ii[p | n] = fma2(w1re, zi, mul2(w1im, zr));
            rr[p]     = fma2(w0re, zr, mul2(w0mn, zi));
            ii[p]     = fma2(w0re, zi, mul2(w0im, zr));
        }
    }
    // State == embedding + layer0 Rots; layer0 CNOT ring absorbed into masks.

    // ---- Layer-1 Rot gates in relabeled basis ----
    apply_l1<0>(rr, ii, lane);
    apply_l1<1>(rr, ii, lane);
    apply_l1<2>(rr, ii, lane);
    apply_l1<3>(rr, ii, lane);
    apply_l1<4>(rr, ii, lane);
    apply_l1<5>(rr, ii, lane);
    apply_l1<6>(rr, ii, lane);
    apply_l1<7>(rr, ii, lane);
    apply_l1<8>(rr, ii, lane);
    apply_l1<9>(rr, ii, lane);
    // Layer-1 CNOT ring absorbed into measurement masks (kM2).

    // ---- Probabilities + Walsh-Hadamard over the 4 p-bits ----
    ull pp[16];
#pragma unroll
    for (int p = 0; p < 16; p++) pp[p] = fma2(rr[p], rr[p], mul2(ii[p], ii[p]));

    const ull kNeg1 = pk2(-1.0f, -1.0f);
#pragma unroll
    for (int b = 1; b < 16; b <<= 1) {
#pragma unroll
        for (int p = 0; p < 16; p++) {
            if (p & b) continue;
            ull u = pp[p], v = pp[p | b];
            pp[p]     = add2(u, v);
            pp[p | b] = fma2(v, kNeg1, u);  // u - v
        }
    }

    float zv[10];
    zv[0] = expz_wht<0>(pp, lane);
    zv[1] = expz_wht<1>(pp, lane);
    zv[2] = expz_wht<2>(pp, lane);
    zv[3] = expz_wht<3>(pp, lane);
    zv[4] = expz_wht<4>(pp, lane);
    zv[5] = expz_wht<5>(pp, lane);
    zv[6] = expz_wht<6>(pp, lane);
    zv[7] = expz_wht<7>(pp, lane);
    zv[8] = expz_wht<8>(pp, lane);
    zv[9] = expz_wht<9>(pp, lane);

    // ---- split-tree warp reduction: 12 SHFLs for all 10 sums ----
    const bool b4 = (lane & 16) != 0;
    const bool b3 = (lane & 8) != 0;
    const bool b2 = (lane & 4) != 0;
    const bool b1 = (lane & 2) != 0;
    const bool b0 = (lane & 1) != 0;

    // step 1 (xor 16): b4=0 lanes own arrays 0..4, b4=1 own 5..9
    float acc0, acc1, acc2, acc3, acc4;
    {
        float s, r;
        s = b4 ? zv[0] : zv[5]; r = __shfl_xor_sync(0xFFFFFFFFu, s, 16);
        acc0 = (b4 ? zv[5] : zv[0]) + r;
        s = b4 ? zv[1] : zv[6]; r = __shfl_xor_sync(0xFFFFFFFFu, s, 16);
        acc1 = (b4 ? zv[6] : zv[1]) + r;
        s = b4 ? zv[2] : zv[7]; r = __shfl_xor_sync(0xFFFFFFFFu, s, 16);
        acc2 = (b4 ? zv[7] : zv[2]) + r;
        s = b4 ? zv[3] : zv[8]; r = __shfl_xor_sync(0xFFFFFFFFu, s, 16);
        acc3 = (b4 ? zv[8] : zv[3]) + r;
        s = b4 ? zv[4] : zv[9]; r = __shfl_xor_sync(0xFFFFFFFFu, s, 16);
        acc4 = (b4 ? zv[9] : zv[4]) + r;
    }

    // step 2 (xor 8): b3=0 keeps {acc0,acc1,acc2}, b3=1 keeps {acc3,acc4}
    float c0, c1, c2;
    {
        float s0 = b3 ? acc0 : acc3;
        float s1 = b3 ? acc1 : acc4;
        float s2 = acc2;  // payload used only from b3=1 side
        float r0 = __shfl_xor_sync(0xFFFFFFFFu, s0, 8);
        float r1 = __shfl_xor_sync(0xFFFFFFFFu, s1, 8);
        float r2 = __shfl_xor_sync(0xFFFFFFFFu, s2, 8);
        c0 = (b3 ? acc3 : acc0) + r0;
        c1 = (b3 ? acc4 : acc1) + r1;
        c2 = b3 ? 0.0f : (acc2 + r2);
    }

    // step 3 (xor 4):
    //  b3=0: b2=0 keeps {c0,c1}; b2=1 keeps {c2}
    //  b3=1: b2=0 keeps {c0};    b2=1 keeps {c1}
    float d0, d1;
    {
        float s0 = b3 ? (b2 ? c0 : c1) : (b2 ? c0 : c2);
        float s1 = c1;  // used only by (b3=0, b2=0) receivers, sent from b2=1 side
        float r0 = __shfl_xor_sync(0xFFFFFFFFu, s0, 4);
        float r1 = __shfl_xor_sync(0xFFFFFFFFu, s1, 4);
        float own = b3 ? (b2 ? c1 : c0) : (b2 ? c2 : c0);
        d0 = own + r0;
        d1 = (!b3 && !b2) ? (c1 + r1) : 0.0f;
    }

    // step 4 (xor 2): only (b3=0,b2=0) lanes still hold 2 arrays
    float e;
    {
        const bool two = (!b3 && !b2);
        float s = two ? (b1 ? d0 : d1) : d0;
        float r = __shfl_xor_sync(0xFFFFFFFFu, s, 2);
        float own = two ? (b1 ? d1 : d0) : d0;
        e = own + r;
    }

    // step 5 (xor 1)
    e += __shfl_xor_sync(0xFFFFFFFFu, e, 1);

    // each lane owns exactly one array; canonical lane writes it
    {
        const int pos = b3 ? (b2 ? 4 : 3) : (b2 ? 2 : (b1 ? 1 : 0));
        const int q = (b4 ? 5 : 0) + pos;
        const bool canon = !b0 && (pos >= 2 ? !b1 : true);
        if (canon) out[warp * N_QUBITS + q] = e;
    }
}

extern "C" void kernel_launch(void* const* d_in, const int* in_sizes, int n_in,
                              void* d_out, int out_size) {
    const float* x  = (const float*)d_in[0];  // [16384, 10]
    const float* qw = (const float*)d_in[1];  // [2, 10, 3]
    float* out = (float*)d_out;               // [16384, 10]

    precompute_rot_kernel<<<1, 32>>>(qw);

    const int threads = 128;                      // 4 warps/block, 5 blocks/SM
    const int blocks  = (BATCH * 32) / threads;   // 4096
    sim_kernel<<<blocks, threads>>>(x, out);
}

// round 13
// speedup vs baseline: 1.6220x; 1.4292x over previous
#include <cuda_runtime.h>
#include <cuda_bf16.h>

// 10-qubit, batch-16384 circuit: RY embedding + 2x StronglyEntanglingLayers.
// R13: TWO warps per sample (64 lanes, 16 amps/lane = 16 ull state regs) for
// ~2x occupancy. Stored-bit layout: h=stored0, p0..p2=stored{1,8,9} (local),
// lane0..4=stored{3..7}, warp=stored2. 2 gates cross warps (smem exchange),
// 5 cross lanes (SHFL), 3 local. GF(2)-relabeled CNOTs, compact Rot coeffs,
// WHT epilogue, packed f32x2 math.

#define N_QUBITS 10
#define BATCH    16384

using ull = unsigned long long;

// ---------------- constexpr GF(2) relabeling ----------------
struct M10 { unsigned r[10]; };

__host__ __device__ constexpr M10 mident() {
    M10 m{}; for (int b = 0; b < 10; b++) m.r[b] = 1u << b; return m;
}
__host__ __device__ constexpr M10 mring(M10 m, int rr) {
    for (int q = 0; q < 10; q++) {
        int t = (q + rr) % 10;
        m.r[9 - t] ^= m.r[9 - q];
    }
    return m;
}
__host__ __device__ constexpr M10 minv(M10 a) {
    M10 inv = mident();
    for (int col = 0; col < 10; col++) {
        int piv = col;
        while (!((a.r[piv] >> col) & 1)) piv++;
        unsigned t = a.r[col]; a.r[col] = a.r[piv]; a.r[piv] = t;
        t = inv.r[col]; inv.r[col] = inv.r[piv]; inv.r[piv] = t;
        for (int r2 = 0; r2 < 10; r2++)
            if (r2 != col && ((a.r[r2] >> col) & 1)) { a.r[r2] ^= a.r[col]; inv.r[r2] ^= inv.r[col]; }
    }
    return inv;
}
__host__ __device__ constexpr unsigned mcol(M10 n, int b) {
    unsigned w = 0;
    for (int sb = 0; sb < 10; sb++) if ((n.r[sb] >> b) & 1) w |= 1u << sb;
    return w;
}
__host__ __device__ constexpr unsigned hibit(unsigned x) {
    unsigned b = 1; while (x >> 1) { x >>= 1; b <<= 1; } return b;
}

constexpr M10 kM1 = mring(mident(), 1);
constexpr M10 kN1 = minv(kM1);
constexpr M10 kM2 = mring(kM1, 2);

// Stored-bit mask decomposition for the new layout:
//   h = stored0; p-bits: p0=stored1, p1=stored8, p2=stored9;
//   lane bits 0..4 = stored 3..7; warp bit = stored2.
__host__ __device__ constexpr unsigned d_h(unsigned M) { return M & 1u; }
__host__ __device__ constexpr unsigned d_p(unsigned M) {
    return ((M >> 1) & 1u) | (((M >> 8) & 1u) << 1) | (((M >> 9) & 1u) << 2);
}
__host__ __device__ constexpr unsigned d_l(unsigned M) { return (M >> 3) & 31u; }
__host__ __device__ constexpr unsigned d_w(unsigned M) { return (M >> 2) & 1u; }

// ---------------- packed f32x2 primitives ----------------
__device__ __forceinline__ ull pk2(float lo, float hi) {
    ull u; asm("mov.b64 %0, {%1, %2};" : "=l"(u) : "f"(lo), "f"(hi)); return u;
}
__device__ __forceinline__ void un2(ull u, float& a, float& b) {
    asm("mov.b64 {%0, %1}, %2;" : "=f"(a), "=f"(b) : "l"(u));
}
__device__ __forceinline__ ull fma2(ull a, ull b, ull c) {
    ull d; asm("fma.rn.f32x2 %0, %1, %2, %3;" : "=l"(d) : "l"(a), "l"(b), "l"(c)); return d;
}
__device__ __forceinline__ ull mul2(ull a, ull b) {
    ull d; asm("mul.rn.f32x2 %0, %1, %2;" : "=l"(d) : "l"(a), "l"(b)); return d;
}
__device__ __forceinline__ ull add2(ull a, ull b) {
    ull d; asm("add.rn.f32x2 %0, %1, %2;" : "=l"(d) : "l"(a), "l"(b)); return d;
}
__device__ __forceinline__ ull shfl64x(ull v, int m) {
    float a, b; un2(v, a, b);
    a = __shfl_xor_sync(0xFFFFFFFFu, a, m);
    b = __shfl_xor_sync(0xFFFFFFFFu, b, m);
    return pk2(a, b);
}
__device__ __forceinline__ ull swap2(ull v) {
    float a, b; un2(v, a, b); return pk2(b, a);
}
__device__ __forceinline__ float2 cmul(float2 a, float2 b) {
    return make_float2(a.x * b.x - a.y * b.y, a.x * b.y + a.y * b.x);
}

// ---------------- precomputed compact Rot coefficients ----------------
__device__ float4 g_rotc[2 * N_QUBITS];

__global__ void precompute_rot_kernel(const float* __restrict__ qw) {
    int i = threadIdx.x;
    if (i < 2 * N_QUBITS) {
        float phi = qw[i * 3 + 0], theta = qw[i * 3 + 1], omega = qw[i * 3 + 2];
        float st, ct;   sincosf(0.5f * theta, &st, &ct);
        float spo, cpo; sincosf(0.5f * (phi + omega), &spo, &cpo);
        float smo, cmo; sincosf(0.5f * (phi - omega), &smo, &cmo);
        g_rotc[i] = make_float4(cpo * ct, spo * ct, cmo * st, smo * st);
    }
}

// ---------------- generalized single-qubit gate (8 packs / lane) ----------------
// Pairs stored s with s^W; role parity(s & R) selects matrix row (sigma).
//   re' = P*ar + S*oi + sigma*(Q*ai - R*or)
//   im' = P*ai - S*or + sigma*(-Q*ar - R*oi)
// SMEM=true: partner data read from psx (16 ull: [0..7]=re, [8..15]=im).
template <unsigned W, unsigned R, bool SMEM>
__device__ __forceinline__ void gate8(ull* rr, ull* ii, const ull* psx,
                                      int lane, int wpair, float4 m) {
    constexpr unsigned hW = d_h(W), pW = d_p(W), lW = d_l(W);
    constexpr unsigned hR = d_h(R), pR = d_p(R), lR = d_l(R), wR = d_w(R);

    unsigned base = (0x96696996u >> (lane & lR)) & 1u;
    if constexpr (wR != 0) base ^= (unsigned)wpair & 1u;
    const float sp = base ? -1.0f : 1.0f;          // sigma, half-lo, p-parity 0
    const float sh = hR ? -sp : sp;                // sigma, half-hi, p-parity 0

    const ull P2  = pk2(m.x, m.x);
    const ull Sv2 = pk2(m.w, m.w);
    const ull nS2 = pk2(-m.w, -m.w);
    const ull QA  = pk2(sp * m.y, sh * m.y);
    const ull nQA = pk2(-sp * m.y, -sh * m.y);
    const ull RA  = pk2(sp * m.z, sh * m.z);
    const ull nRA = pk2(-sp * m.z, -sh * m.z);

#define CUPD(nre, nim, are, aie, ore, oie, PAR)                       \
    {                                                                 \
        ull Qp_ = (PAR) ? nQA : QA;                                   \
        ull Qm_ = (PAR) ? QA : nQA;                                   \
        ull Rp_ = (PAR) ? RA : nRA;                                   \
        ull t1_ = fma2(Qp_, (aie), mul2(Rp_, (ore)));                 \
        ull t2_ = fma2(Qm_, (are), mul2(Rp_, (oie)));                 \
        (nre) = fma2(P2, (are), fma2(Sv2, (oie), t1_));               \
        (nim) = fma2(P2, (aie), fma2(nS2, (ore), t2_));               \
    }

    if constexpr (SMEM) {
        // partner snapshot is stable in smem: simple in-place loop
#pragma unroll
        for (int p = 0; p < 8; p++) {
            ull ore = psx[p ^ pW], oie = psx[8 + (p ^ pW)];
            if constexpr (hW) { ore = swap2(ore); oie = swap2(oie); }
            const bool PAR = ((0x6996u >> (p & pR)) & 1u) != 0;
            ull nre, nim;
            CUPD(nre, nim, rr[p], ii[p], ore, oie, PAR);
            rr[p] = nre; ii[p] = nim;
        }
    } else if constexpr (pW == 0) {
#pragma unroll
        for (int p = 0; p < 8; p++) {
            ull ore = rr[p], oie = ii[p];
            if constexpr (lW != 0) { ore = shfl64x(ore, (int)lW); oie = shfl64x(oie, (int)lW); }
            if constexpr (hW)      { ore = swap2(ore); oie = swap2(oie); }
            const bool PAR = ((0x6996u >> (p & pR)) & 1u) != 0;
            ull nre, nim;
            CUPD(nre, nim, rr[p], ii[p], ore, oie, PAR);
            rr[p] = nre; ii[p] = nim;
        }
    } else {
        constexpr unsigned selbit = hibit(pW);
#pragma unroll
        for (int p = 0; p < 8; p++) {
            if (p & (int)selbit) continue;
            const int p2 = p ^ (int)pW;
            ull oa_re = rr[p2], oa_ie = ii[p2];   // "other" for p
            ull ob_re = rr[p],  ob_ie = ii[p];    // "other" for p2
            if constexpr (lW != 0) {
                oa_re = shfl64x(oa_re, (int)lW); oa_ie = shfl64x(oa_ie, (int)lW);
                ob_re = shfl64x(ob_re, (int)lW); ob_ie = shfl64x(ob_ie, (int)lW);
            }
            if constexpr (hW) {
                oa_re = swap2(oa_re); oa_ie = swap2(oa_ie);
                ob_re = swap2(ob_re); ob_ie = swap2(ob_ie);
            }
            const bool pA = ((0x6996u >> (p  & pR)) & 1u) != 0;
            const bool pC = ((0x6996u >> (p2 & pR)) & 1u) != 0;
            ull nre1, nim1, nre2, nim2;
            CUPD(nre1, nim1, rr[p],  ii[p],  oa_re, oa_ie, pA);
            CUPD(nre2, nim2, rr[p2], ii[p2], ob_re, ob_ie, pC);
            rr[p] = nre1; ii[p] = nim1; rr[p2] = nre2; ii[p2] = nim2;
        }
    }
#undef CUPD
}

// Layer-1 Rot on wire Q (phys bit 9-Q) — in-warp variant.
template <int Q>
__device__ __forceinline__ void apply_l1(ull* rr, ull* ii, int lane, int wpair) {
    constexpr int b = 9 - Q;
    constexpr unsigned W = mcol(kN1, b);
    constexpr unsigned R = kM1.r[b];
    static_assert(d_w(W) == 0, "in-warp gate must not cross warps");
    float4 m = __ldg(&g_rotc[N_QUBITS + Q]);
    gate8<W, R, false>(rr, ii, nullptr, lane, wpair, m);
}

// Layer-1 Rot on wire Q — cross-warp variant (partner state in smem).
template <int Q>
__device__ __forceinline__ void apply_l1_smem(ull* rr, ull* ii, const ull* psx,
                                              int lane, int wpair) {
    constexpr int b = 9 - Q;
    constexpr unsigned W = mcol(kN1, b);
    constexpr unsigned R = kM1.r[b];
    static_assert(d_w(W) == 1, "smem gate must cross warps");
    float4 m = __ldg(&g_rotc[N_QUBITS + Q]);
    gate8<W, R, true>(rr, ii, psx, lane, wpair, m);
}

// <Z_wireQ> from WHT array.
template <int Q>
__device__ __forceinline__ float expz_wht(const ull* pp, int lane, int wpair) {
    constexpr unsigned mr = kM2.r[9 - Q];
    constexpr unsigned hM = d_h(mr), pM = d_p(mr), lM = d_l(mr), wM = d_w(mr);
    float a, b; un2(pp[pM], a, b);
    float z = hM ? (a - b) : (a + b);
    unsigned s = (0x96696996u >> (lane & lM)) & 1u;
    if constexpr (wM != 0) s ^= (unsigned)wpair & 1u;
    if (s) z = -z;
    return z;
}

// ---------------- main kernel: one sample per 2-warp block ----------------
__global__ void __launch_bounds__(64)
sim_kernel(const float* __restrict__ x, float* __restrict__ out) {
    const int sample = blockIdx.x;
    const int lane  = threadIdx.x & 31;
    const int wpair = threadIdx.x >> 5;   // 0 or 1

    // padded exchange buffer: [warp][lane][16 ull + 1 pad]
    __shared__ ull sx[2][32][17];
    __shared__ float zb[2][10];

    const float* xs = x + sample * N_QUBITS;

    // ---- Prologue ----
    // factor for wire q, bit v: f0/f1 from g_rotc[q] (= Rot(l0,q) * RY(x_q) |0/1>)
    // f0 = (P c - R s, -(Q c + S s)); f1 = (R c + P s, Q s - S c)
    // warp bit = wire 7; lane bit j = wire 6-j; h = wire 9; p0,p1,p2 = wires 8,1,0.
    float2 mfac;
    {
        float s, c; __sincosf(0.5f * __ldg(&xs[7]), &s, &c);
        float4 m = __ldg(&g_rotc[7]);
        mfac = wpair
            ? make_float2(fmaf(m.z, c, m.x * s), fmaf(m.y, s, -m.w * c))
            : make_float2(fmaf(m.x, c, -m.z * s), -fmaf(m.y, c, m.w * s));
    }
#pragma unroll
    for (int j = 0; j < 5; j++) {
        const int q = 6 - j;
        float s, c; __sincosf(0.5f * __ldg(&xs[q]), &s, &c);
        float4 m = __ldg(&g_rotc[q]);
        float2 f;
        if ((lane >> j) & 1)
            f = make_float2(fmaf(m.z, c, m.x * s), fmaf(m.y, s, -m.w * c));
        else
            f = make_float2(fmaf(m.x, c, -m.z * s), -fmaf(m.y, c, m.w * s));
        mfac = cmul(mfac, f);
    }

    ull rr[8], ii[8];
    {
        float s, c; __sincosf(0.5f * __ldg(&xs[9]), &s, &c);
        float4 m = __ldg(&g_rotc[9]);
        float2 f0 = make_float2(fmaf(m.x, c, -m.z * s), -fmaf(m.y, c, m.w * s));
        float2 f1 = make_float2(fmaf(m.z, c, m.x * s), fmaf(m.y, s, -m.w * c));
        float2 a0 = cmul(f0, mfac);
        float2 a1 = cmul(f1, mfac);
        rr[0] = pk2(a0.x, a1.x); ii[0] = pk2(a0.y, a1.y);
    }
    // tree expansion: p bit j over wires {8, 1, 0}
    {
        const int wq[3] = {8, 1, 0};
#pragma unroll
        for (int j = 0; j < 3; j++) {
            const int n = 1 << j;
            float s, c; __sincosf(0.5f * __ldg(&xs[wq[j]]), &s, &c);
            float4 m = __ldg(&g_rotc[wq[j]]);
            float2 w0 = make_float2(fmaf(m.x, c, -m.z * s), -fmaf(m.y, c, m.w * s));
            float2 w1 = make_float2(fmaf(m.z, c, m.x * s), fmaf(m.y, s, -m.w * c));
            ull w0re = pk2(w0.x, w0.x), w0im = pk2(w0.y, w0.y), w0mn = pk2(-w0.y, -w0.y);
            ull w1re = pk2(w1.x, w1.x), w1im = pk2(w1.y, w1.y), w1mn = pk2(-w1.y, -w1.y);
#pragma unroll
            for (int p = 0; p < 8; p++) {
                if (p >= n) continue;
                ull zr = rr[p], zi = ii[p];
                rr[p | n] = fma2(w1re, zr, mul2(w1mn, zi));
                ii[p | n] = fma2(w1re, zi, mul2(w1im, zr));
                rr[p]     = fma2(w0re, zr, mul2(w0mn, zi));
                ii[p]     = fma2(w0re, zi, mul2(w0im, zr));
            }
        }
    }
    // State == embedding + layer-0 Rots; layer-0 CNOT ring absorbed into masks.

    // ---- Layer-1 gates ----
    // Cross-warp gate 1: wire 7 (phys bit 2, W={stored1,stored2}): partner lane = lane.
    {
        ull* slot = &sx[wpair][lane][0];
#pragma unroll
        for (int k = 0; k < 8; k++) { slot[k] = rr[k]; slot[8 + k] = ii[k]; }
    }
    __syncthreads();
    apply_l1_smem<7>(rr, ii, &sx[wpair ^ 1][lane][0], lane, wpair);
    __syncthreads();
    // Cross-warp gate 2: wire 6 (phys bit 3, W={stored2,stored3}): partner lane = lane^1.
    {
        ull* slot = &sx[wpair][lane][0];
#pragma unroll
        for (int k = 0; k < 8; k++) { slot[k] = rr[k]; slot[8 + k] = ii[k]; }
    }
    __syncthreads();
    apply_l1_smem<6>(rr, ii, &sx[wpair ^ 1][lane ^ 1][0], lane, wpair);

    // In-warp gates (commuting; interleave shfl-heavy with local for scheduling)
    apply_l1<5>(rr, ii, lane, wpair);   // b=4: shfl xor 3
    apply_l1<0>(rr, ii, lane, wpair);   // b=9: local pack-pairs
    apply_l1<4>(rr, ii, lane, wpair);   // b=5: shfl xor 6
    apply_l1<9>(rr, ii, lane, wpair);   // b=0: local (h+p)
    apply_l1<3>(rr, ii, lane, wpair);   // b=6: shfl xor 12
    apply_l1<8>(rr, ii, lane, wpair);   // b=1: local (h+p)
    apply_l1<2>(rr, ii, lane, wpair);   // b=7: shfl xor 24
    apply_l1<1>(rr, ii, lane, wpair);   // b=8: shfl xor 16 + pack-xor
    // Layer-1 CNOT ring absorbed into measurement masks (kM2).

    // ---- Probabilities + WHT over the 3 p-bits ----
    ull pp[8];
#pragma unroll
    for (int p = 0; p < 8; p++) pp[p] = fma2(rr[p], rr[p], mul2(ii[p], ii[p]));

    const ull kNeg1 = pk2(-1.0f, -1.0f);
#pragma unroll
    for (int b = 1; b < 8; b <<= 1) {
#pragma unroll
        for (int p = 0; p < 8; p++) {
            if (p & b) continue;
            ull u = pp[p], v = pp[p | b];
            pp[p]     = add2(u, v);
            pp[p | b] = fma2(v, kNeg1, u);  // u - v
        }
    }

    float zv[10];
    zv[0] = expz_wht<0>(pp, lane, wpair);
    zv[1] = expz_wht<1>(pp, lane, wpair);
    zv[2] = expz_wht<2>(pp, lane, wpair);
    zv[3] = expz_wht<3>(pp, lane, wpair);
    zv[4] = expz_wht<4>(pp, lane, wpair);
    zv[5] = expz_wht<5>(pp, lane, wpair);
    zv[6] = expz_wht<6>(pp, lane, wpair);
    zv[7] = expz_wht<7>(pp, lane, wpair);
    zv[8] = expz_wht<8>(pp, lane, wpair);
    zv[9] = expz_wht<9>(pp, lane, wpair);

    // ---- split-tree warp reduction: 12 SHFLs for all 10 sums ----
    const bool b4 = (lane & 16) != 0;
    const bool b3 = (lane & 8) != 0;
    const bool b2 = (lane & 4) != 0;
    const bool b1 = (lane & 2) != 0;
    const bool b0 = (lane & 1) != 0;

    float acc0, acc1, acc2, acc3, acc4;
    {
        float s, r;
        s = b4 ? zv[0] : zv[5]; r = __shfl_xor_sync(0xFFFFFFFFu, s, 16);
        acc0 = (b4 ? zv[5] : zv[0]) + r;
        s = b4 ? zv[1] : zv[6]; r = __shfl_xor_sync(0xFFFFFFFFu, s, 16);
        acc1 = (b4 ? zv[6] : zv[1]) + r;
        s = b4 ? zv[2] : zv[7]; r = __shfl_xor_sync(0xFFFFFFFFu, s, 16);
        acc2 = (b4 ? zv[7] : zv[2]) + r;
        s = b4 ? zv[3] : zv[8]; r = __shfl_xor_sync(0xFFFFFFFFu, s, 16);
        acc3 = (b4 ? zv[8] : zv[3]) + r;
        s = b4 ? zv[4] : zv[9]; r = __shfl_xor_sync(0xFFFFFFFFu, s, 16);
        acc4 = (b4 ? zv[9] : zv[4]) + r;
    }
    float c0, c1, c2;
    {
        float s0 = b3 ? acc0 : acc3;
        float s1 = b3 ? acc1 : acc4;
        float s2 = acc2;
        float r0 = __shfl_xor_sync(0xFFFFFFFFu, s0, 8);
        float r1 = __shfl_xor_sync(0xFFFFFFFFu, s1, 8);
        float r2 = __shfl_xor_sync(0xFFFFFFFFu, s2, 8);
        c0 = (b3 ? acc3 : acc0) + r0;
        c1 = (b3 ? acc4 : acc1) + r1;
        c2 = b3 ? 0.0f : (acc2 + r2);
    }
    float d0, d1;
    {
        float s0 = b3 ? (b2 ? c0 : c1) : (b2 ? c0 : c2);
        float s1 = c1;
        float r0 = __shfl_xor_sync(0xFFFFFFFFu, s0, 4);
        float r1 = __shfl_xor_sync(0xFFFFFFFFu, s1, 4);
        float own = b3 ? (b2 ? c1 : c0) : (b2 ? c2 : c0);
        d0 = own + r0;
        d1 = (!b3 && !b2) ? (c1 + r1) : 0.0f;
    }
    float e;
    {
        const bool two = (!b3 && !b2);
        float s = two ? (b1 ? d0 : d1) : d0;
        float r = __shfl_xor_sync(0xFFFFFFFFu, s, 2);
        float own = two ? (b1 ? d1 : d0) : d0;
        e = own + r;
    }
    e += __shfl_xor_sync(0xFFFFFFFFu, e, 1);

    // per-warp partial -> smem; warp 0 combines
    const int pos = b3 ? (b2 ? 4 : 3) : (b2 ? 2 : (b1 ? 1 : 0));
    const int q = (b4 ? 5 : 0) + pos;
    const bool canon = !b0 && (pos >= 2 ? !b1 : true);
    if (canon) zb[wpair][q] = e;
    __syncthreads();
    if (wpair == 0 && canon)
        out[sample * N_QUBITS + q] = zb[0][q] + zb[1][q];
}

extern "C" void kernel_launch(void* const* d_in, const int* in_sizes, int n_in,
                              void* d_out, int out_size) {
    const float* x  = (const float*)d_in[0];  // [16384, 10]
    const float* qw = (const float*)d_in[1];  // [2, 10, 3]
    float* out = (float*)d_out;               // [16384, 10]

    precompute_rot_kernel<<<1, 32>>>(qw);

    sim_kernel<<<BATCH, 64>>>(x, out);        // one sample per 2-warp block
}